// round 1
// baseline (speedup 1.0000x reference)
#include <cuda_runtime.h>
#include <cuda_bf16.h>
#include <math.h>

// Problem constants
#define B_    2
#define S_    2048
#define HID_  512
#define H_    8
#define D_    64
#define BH_   (B_ * H_)          // 16
#define M_    (B_ * S_)          // 4096 rows for projections

// ---------------------------------------------------------------------------
// Scratch (no allocation allowed): Qh/Kh/Vh in [B,H,S,D], x merged [B,S,HID],
// and a fallback attn buffer in case the harness output only contains `out`.
// ---------------------------------------------------------------------------
__device__ float g_Qh[BH_ * S_ * D_];          // 8 MB
__device__ float g_Kh[BH_ * S_ * D_];          // 8 MB
__device__ float g_Vh[BH_ * S_ * D_];          // 8 MB
__device__ float g_X [M_ * HID_];              // 8 MB
__device__ float g_attn_scratch[(size_t)BH_ * S_ * S_];  // 256 MB fallback

// ---------------------------------------------------------------------------
// Projection GEMM: Y = X @ W^T + b.  X:[4096,512], W:[512,512] row-major.
// NT layout (both operands K-contiguous). 64x64 tile, BK=16, 4x4 microtile.
// head_split=1 -> write to [B,H,S,D]; else write [M,512] row-major.
// ---------------------------------------------------------------------------
__global__ void __launch_bounds__(256)
proj_kernel(const float* __restrict__ X, const float* __restrict__ W,
            const float* __restrict__ bias, float* __restrict__ Y,
            int head_split)
{
    const int K = HID_;
    const int m0 = blockIdx.y * 64;
    const int n0 = blockIdx.x * 64;

    __shared__ float As[16][68];
    __shared__ float Bs[16][68];

    const int tid = threadIdx.x;
    const int tx = tid & 15;
    const int ty = tid >> 4;

    float acc[4][4] = {};

    for (int k0 = 0; k0 < K; k0 += 16) {
        #pragma unroll
        for (int i = 0; i < 4; i++) {
            int idx = tid + i * 256;
            int mm = idx >> 4, kk = idx & 15;
            As[kk][mm] = X[(size_t)(m0 + mm) * K + k0 + kk];
            Bs[kk][mm] = W[(size_t)(n0 + mm) * K + k0 + kk];
        }
        __syncthreads();
        #pragma unroll
        for (int kk = 0; kk < 16; kk++) {
            float a[4], b[4];
            #pragma unroll
            for (int i = 0; i < 4; i++) a[i] = As[kk][ty * 4 + i];
            #pragma unroll
            for (int j = 0; j < 4; j++) b[j] = Bs[kk][tx * 4 + j];
            #pragma unroll
            for (int i = 0; i < 4; i++)
                #pragma unroll
                for (int j = 0; j < 4; j++)
                    acc[i][j] += a[i] * b[j];
        }
        __syncthreads();
    }

    #pragma unroll
    for (int i = 0; i < 4; i++) {
        int m = m0 + ty * 4 + i;
        #pragma unroll
        for (int j = 0; j < 4; j++) {
            int n = n0 + tx * 4 + j;
            float val = acc[i][j] + bias[n];
            if (head_split) {
                int b  = m >> 11;        // m / 2048
                int s  = m & 2047;
                int h  = n >> 6;         // n / 64
                int d  = n & 63;
                Y[(((size_t)(b * H_ + h)) * S_ + s) * D_ + d] = val;
            } else {
                Y[(size_t)m * HID_ + n] = val;
            }
        }
    }
}

// ---------------------------------------------------------------------------
// Scores: attn_raw[z,q,k] = scale * Qh[z,q,:] . Kh[z,k,:]   (z = b*H+h)
// + mask application. NT GEMM, M=N=2048, K=64.
// ---------------------------------------------------------------------------
__global__ void __launch_bounds__(256)
scores_kernel(const float* __restrict__ Qh, const float* __restrict__ Kh,
              const int* __restrict__ mask, float* __restrict__ attn)
{
    const int K = D_;
    const int z = blockIdx.z;
    const int bb = z >> 3;  // batch

    const float* A  = Qh + (size_t)z * S_ * D_;
    const float* Bm = Kh + (size_t)z * S_ * D_;

    const int m0 = blockIdx.y * 64;
    const int n0 = blockIdx.x * 64;

    __shared__ float As[16][68];
    __shared__ float Bs[16][68];

    const int tid = threadIdx.x;
    const int tx = tid & 15;
    const int ty = tid >> 4;

    float acc[4][4] = {};

    for (int k0 = 0; k0 < K; k0 += 16) {
        #pragma unroll
        for (int i = 0; i < 4; i++) {
            int idx = tid + i * 256;
            int mm = idx >> 4, kk = idx & 15;
            As[kk][mm] = A [(size_t)(m0 + mm) * K + k0 + kk];
            Bs[kk][mm] = Bm[(size_t)(n0 + mm) * K + k0 + kk];
        }
        __syncthreads();
        #pragma unroll
        for (int kk = 0; kk < 16; kk++) {
            float a[4], b[4];
            #pragma unroll
            for (int i = 0; i < 4; i++) a[i] = As[kk][ty * 4 + i];
            #pragma unroll
            for (int j = 0; j < 4; j++) b[j] = Bs[kk][tx * 4 + j];
            #pragma unroll
            for (int i = 0; i < 4; i++)
                #pragma unroll
                for (int j = 0; j < 4; j++)
                    acc[i][j] += a[i] * b[j];
        }
        __syncthreads();
    }

    const float scale = 0.125f;  // 1/sqrt(64)
    #pragma unroll
    for (int i = 0; i < 4; i++) {
        int m = m0 + ty * 4 + i;
        #pragma unroll
        for (int j = 0; j < 4; j++) {
            int n = n0 + tx * 4 + j;
            float val = acc[i][j] * scale;
            size_t mi = ((size_t)bb * S_ + m) * S_ + n;
            if (mask[mi] == 0) val = -1e10f;
            attn[((size_t)z * S_ + m) * S_ + n] = val;
        }
    }
}

// ---------------------------------------------------------------------------
// Row softmax over last dim (2048). One block per row, 8 elems per thread,
// kept in registers: one read + one write of the 268 MB attn tensor.
// ---------------------------------------------------------------------------
__global__ void __launch_bounds__(256)
softmax_kernel(float* __restrict__ attn)
{
    const size_t row = blockIdx.x;
    float* p = attn + row * S_;
    const int t = threadIdx.x;

    float v[8];
    float m = -INFINITY;
    #pragma unroll
    for (int i = 0; i < 8; i++) {
        v[i] = p[t + i * 256];
        m = fmaxf(m, v[i]);
    }

    __shared__ float red[256];
    red[t] = m;
    __syncthreads();
    #pragma unroll
    for (int s = 128; s > 0; s >>= 1) {
        if (t < s) red[t] = fmaxf(red[t], red[t + s]);
        __syncthreads();
    }
    m = red[0];
    __syncthreads();

    float sum = 0.f;
    #pragma unroll
    for (int i = 0; i < 8; i++) {
        v[i] = __expf(v[i] - m);
        sum += v[i];
    }
    red[t] = sum;
    __syncthreads();
    #pragma unroll
    for (int s = 128; s > 0; s >>= 1) {
        if (t < s) red[t] += red[t + s];
        __syncthreads();
    }
    float inv = 1.0f / red[0];

    #pragma unroll
    for (int i = 0; i < 8; i++)
        p[t + i * 256] = v[i] * inv;
}

// ---------------------------------------------------------------------------
// PV: x[z,q,d] = sum_k attn[z,q,k] * Vh[z,k,d].  NN GEMM, M=2048, N=64, K=2048.
// Epilogue merges heads back to [B,S,HID].
// ---------------------------------------------------------------------------
__global__ void __launch_bounds__(256)
pv_kernel(const float* __restrict__ attn, const float* __restrict__ Vh,
          float* __restrict__ Xout)
{
    const int z = blockIdx.z;
    const int bb = z >> 3;
    const int hh = z & 7;

    const float* A  = attn + (size_t)z * S_ * S_;   // [2048, 2048]
    const float* Bv = Vh   + (size_t)z * S_ * D_;   // [2048, 64]

    const int m0 = blockIdx.y * 64;

    __shared__ float As[16][68];
    __shared__ float Bs[16][68];

    const int tid = threadIdx.x;
    const int tx = tid & 15;
    const int ty = tid >> 4;

    float acc[4][4] = {};

    for (int k0 = 0; k0 < S_; k0 += 16) {
        #pragma unroll
        for (int i = 0; i < 4; i++) {
            int idx = tid + i * 256;
            int mm = idx >> 4, kk = idx & 15;
            As[kk][mm] = A[(size_t)(m0 + mm) * S_ + k0 + kk];
            int nn = idx & 63, kk2 = idx >> 6;
            Bs[kk2][nn] = Bv[(size_t)(k0 + kk2) * D_ + nn];
        }
        __syncthreads();
        #pragma unroll
        for (int kk = 0; kk < 16; kk++) {
            float a[4], b[4];
            #pragma unroll
            for (int i = 0; i < 4; i++) a[i] = As[kk][ty * 4 + i];
            #pragma unroll
            for (int j = 0; j < 4; j++) b[j] = Bs[kk][tx * 4 + j];
            #pragma unroll
            for (int i = 0; i < 4; i++)
                #pragma unroll
                for (int j = 0; j < 4; j++)
                    acc[i][j] += a[i] * b[j];
        }
        __syncthreads();
    }

    #pragma unroll
    for (int i = 0; i < 4; i++) {
        int m = m0 + ty * 4 + i;          // q position
        #pragma unroll
        for (int j = 0; j < 4; j++) {
            int d = tx * 4 + j;
            Xout[((size_t)bb * S_ + m) * HID_ + hh * D_ + d] = acc[i][j];
        }
    }
}

// ---------------------------------------------------------------------------
// Launch
// ---------------------------------------------------------------------------
extern "C" void kernel_launch(void* const* d_in, const int* in_sizes, int n_in,
                              void* d_out, int out_size)
{
    const float* q    = (const float*)d_in[0];
    const float* k    = (const float*)d_in[1];
    const float* v    = (const float*)d_in[2];
    const int*   mask = (const int*)  d_in[3];
    const float* Wq   = (const float*)d_in[4];
    const float* bq   = (const float*)d_in[5];
    const float* Wk   = (const float*)d_in[6];
    const float* bk   = (const float*)d_in[7];
    const float* Wv   = (const float*)d_in[8];
    const float* bv   = (const float*)d_in[9];
    const float* Wo   = (const float*)d_in[10];
    const float* bo   = (const float*)d_in[11];

    float* out = (float*)d_out;

    // Resolve scratch device-global addresses
    float *Qh, *Kh, *Vh, *X, *attn_scratch;
    cudaGetSymbolAddress((void**)&Qh, g_Qh);
    cudaGetSymbolAddress((void**)&Kh, g_Kh);
    cudaGetSymbolAddress((void**)&Vh, g_Vh);
    cudaGetSymbolAddress((void**)&X,  g_X);
    cudaGetSymbolAddress((void**)&attn_scratch, g_attn_scratch);

    const size_t out_elems  = (size_t)M_ * HID_;           // 2,097,152
    const size_t attn_elems = (size_t)BH_ * S_ * S_;       // 67,108,864
    float* attn = ((size_t)out_size >= out_elems + attn_elems)
                      ? out + out_elems
                      : attn_scratch;

    dim3 blk(256);

    // 1) Q/K/V projections, head-split fused into epilogue
    dim3 gproj(HID_ / 64, M_ / 64);     // (8, 64)
    proj_kernel<<<gproj, blk>>>(q, Wq, bq, Qh, 1);
    proj_kernel<<<gproj, blk>>>(k, Wk, bk, Kh, 1);
    proj_kernel<<<gproj, blk>>>(v, Wv, bv, Vh, 1);

    // 2) Scores + scale + mask
    dim3 gsc(S_ / 64, S_ / 64, BH_);    // (32, 32, 16)
    scores_kernel<<<gsc, blk>>>(Qh, Kh, mask, attn);

    // 3) Softmax over rows
    softmax_kernel<<<(unsigned)(BH_ * S_), blk>>>(attn);

    // 4) PV + head merge
    dim3 gpv(1, S_ / 64, BH_);          // (1, 32, 16)
    pv_kernel<<<gpv, blk>>>(attn, Vh, X);

    // 5) Output projection
    proj_kernel<<<gproj, blk>>>(X, Wo, bo, out, 0);
}

// round 2
// speedup vs baseline: 1.5527x; 1.5527x over previous
#include <cuda_runtime.h>
#include <math.h>

#define B_    2
#define S_    2048
#define HID_  512
#define H_    8
#define D_    64
#define BH_   16
#define M_    4096

// Scratch (device globals; no allocation allowed)
__device__ float g_Qh[M_ * HID_];
__device__ float g_Kh[M_ * HID_];
__device__ float g_Vh[M_ * HID_];
__device__ float g_X [M_ * HID_];
__device__ float g_attn_scratch[(size_t)BH_ * S_ * S_];

// ---------------------------------------------------------------------------
// tf32 helpers
// ---------------------------------------------------------------------------
__device__ __forceinline__ unsigned f2tf(float x) {
    unsigned u;
    asm("cvt.rna.tf32.f32 %0, %1;" : "=r"(u) : "f"(x));
    return u;
}
__device__ __forceinline__ float f2tff(float x) { return __uint_as_float(f2tf(x)); }

// D += A(16x8,row) * B(8x8,col)   tf32 in, fp32 accum
__device__ __forceinline__ void mma8(float c[4], const unsigned a[4], const unsigned b[2]) {
    asm volatile(
        "mma.sync.aligned.m16n8k8.row.col.f32.tf32.tf32.f32 "
        "{%0,%1,%2,%3},{%4,%5,%6,%7},{%8,%9},{%0,%1,%2,%3};"
        : "+f"(c[0]), "+f"(c[1]), "+f"(c[2]), "+f"(c[3])
        : "r"(a[0]), "r"(a[1]), "r"(a[2]), "r"(a[3]),
          "r"(b[0]), "r"(b[1]));
}

// ---------------------------------------------------------------------------
// Projection GEMM (tf32 tensor): Y[m][n] = sum_k X[m][k]*W[n][k] + bias[n]
// Block tile 128m x 64n, k-tile 32. 8 warps: warp = 32m x 32n.
// ---------------------------------------------------------------------------
__global__ void __launch_bounds__(256)
proj_tf32(const float* __restrict__ Xg, const float* __restrict__ Wg,
          const float* __restrict__ bias, float* __restrict__ Y)
{
    __shared__ float As[128 * 36];   // padded stride 36 -> conflict-free frags
    __shared__ float Bs[64 * 36];

    const int tid = threadIdx.x;
    const int lane = tid & 31, wid = tid >> 5;
    const int g = lane >> 2, tg = lane & 3;
    const int wm = wid & 3, wn = wid >> 2;
    const int m0 = blockIdx.y * 128, n0 = blockIdx.x * 64;

    float acc[2][4][4] = {};

    for (int k0 = 0; k0 < 512; k0 += 32) {
        #pragma unroll
        for (int jj = 0; jj < 4; jj++) {
            int lin = tid + jj * 256;
            int r = lin >> 3, c4 = lin & 7;
            float4 v = *(const float4*)(Xg + (size_t)(m0 + r) * 512 + k0 + c4 * 4);
            float* d = &As[r * 36 + c4 * 4];
            d[0] = f2tff(v.x); d[1] = f2tff(v.y); d[2] = f2tff(v.z); d[3] = f2tff(v.w);
        }
        #pragma unroll
        for (int jj = 0; jj < 2; jj++) {
            int lin = tid + jj * 256;
            int r = lin >> 3, c4 = lin & 7;
            float4 v = *(const float4*)(Wg + (size_t)(n0 + r) * 512 + k0 + c4 * 4);
            float* d = &Bs[r * 36 + c4 * 4];
            d[0] = f2tff(v.x); d[1] = f2tff(v.y); d[2] = f2tff(v.z); d[3] = f2tff(v.w);
        }
        __syncthreads();

        #pragma unroll
        for (int ks = 0; ks < 4; ks++) {
            unsigned af[2][4], bf[4][2];
            #pragma unroll
            for (int mi = 0; mi < 2; mi++) {
                int rb = wm * 32 + mi * 16;
                af[mi][0] = __float_as_uint(As[(rb + g    ) * 36 + ks * 8 + tg    ]);
                af[mi][1] = __float_as_uint(As[(rb + g + 8) * 36 + ks * 8 + tg    ]);
                af[mi][2] = __float_as_uint(As[(rb + g    ) * 36 + ks * 8 + tg + 4]);
                af[mi][3] = __float_as_uint(As[(rb + g + 8) * 36 + ks * 8 + tg + 4]);
            }
            #pragma unroll
            for (int ni = 0; ni < 4; ni++) {
                int rb = wn * 32 + ni * 8;
                bf[ni][0] = __float_as_uint(Bs[(rb + g) * 36 + ks * 8 + tg    ]);
                bf[ni][1] = __float_as_uint(Bs[(rb + g) * 36 + ks * 8 + tg + 4]);
            }
            #pragma unroll
            for (int mi = 0; mi < 2; mi++)
                #pragma unroll
                for (int ni = 0; ni < 4; ni++)
                    mma8(acc[mi][ni], af[mi], bf[ni]);
        }
        __syncthreads();
    }

    #pragma unroll
    for (int mi = 0; mi < 2; mi++) {
        int r0 = m0 + wm * 32 + mi * 16 + g;
        #pragma unroll
        for (int ni = 0; ni < 4; ni++) {
            int c0 = n0 + wn * 32 + ni * 8 + 2 * tg;
            float b0v = __ldg(bias + c0), b1v = __ldg(bias + c0 + 1);
            Y[(size_t)r0 * 512 + c0    ] = acc[mi][ni][0] + b0v;
            Y[(size_t)r0 * 512 + c0 + 1] = acc[mi][ni][1] + b1v;
            Y[(size_t)(r0 + 8) * 512 + c0    ] = acc[mi][ni][2] + b0v;
            Y[(size_t)(r0 + 8) * 512 + c0 + 1] = acc[mi][ni][3] + b1v;
        }
    }
}

// ---------------------------------------------------------------------------
// Fused attention: scores (tf32 mma) + scale + mask + exp (no-max softmax,
// scores are O(10) so exp is safe) + online rowsum + PV (tf32 mma) +
// single normalized attn write.
// One block = (z = b*H+h, 16-row q strip). P strip (16 x 2048 fp32) in smem.
// ---------------------------------------------------------------------------
#define PSTR 2052
#define KSTR 68
#define VSTR 72

__global__ void __launch_bounds__(256)
attn_fused(const float* __restrict__ Qf, const float* __restrict__ Kf,
           const float* __restrict__ Vf, const int* __restrict__ mask,
           float* __restrict__ attn, float* __restrict__ Xo)
{
    extern __shared__ float sm[];
    float* P      = sm;                       // 16 * 2052
    float* Kt     = P  + 16 * PSTR;           // 128 * 68
    float* Vt     = Kt + 128 * KSTR;          // 128 * 72
    float* Qt     = Vt + 128 * VSTR;          // 16 * 68
    float* rowsum = Qt + 16 * KSTR;           // 16

    const int tid = threadIdx.x, lane = tid & 31, wid = tid >> 5;
    const int g = lane >> 2, tg = lane & 3;
    const int z = blockIdx.y, strip = blockIdx.x;
    const int bB = z >> 3, h = z & 7;
    const int s0 = strip * 16;

    // stage Q strip (16x64), tf32-rounded
    {
        int r = tid >> 4, c4 = tid & 15;
        float4 v = *(const float4*)(Qf + (size_t)(bB * S_ + s0 + r) * HID_ + h * 64 + c4 * 4);
        float* d = &Qt[r * KSTR + c4 * 4];
        d[0] = f2tff(v.x); d[1] = f2tff(v.y); d[2] = f2tff(v.z); d[3] = f2tff(v.w);
    }
    if (tid < 16) rowsum[tid] = 0.f;
    __syncthreads();

    // persistent A fragments for scores (Q strip, k = 64 head dim)
    unsigned qa[8][4];
    #pragma unroll
    for (int ks = 0; ks < 8; ks++) {
        qa[ks][0] = __float_as_uint(Qt[(g    ) * KSTR + ks * 8 + tg    ]);
        qa[ks][1] = __float_as_uint(Qt[(g + 8) * KSTR + ks * 8 + tg    ]);
        qa[ks][2] = __float_as_uint(Qt[(g    ) * KSTR + ks * 8 + tg + 4]);
        qa[ks][3] = __float_as_uint(Qt[(g + 8) * KSTR + ks * 8 + tg + 4]);
    }

    float pv[4] = {0.f, 0.f, 0.f, 0.f};   // warp owns 16 x 8 of PV output

    for (int it = 0; it < 16; it++) {
        const int kbase = it * 128;

        // stage K,V tiles (128 x 64 each), tf32-rounded
        #pragma unroll
        for (int jj = 0; jj < 8; jj++) {
            int lin = tid + jj * 256;
            int r = lin >> 4, c4 = lin & 15;
            float4 kv = *(const float4*)(Kf + (size_t)(bB * S_ + kbase + r) * HID_ + h * 64 + c4 * 4);
            float* d = &Kt[r * KSTR + c4 * 4];
            d[0] = f2tff(kv.x); d[1] = f2tff(kv.y); d[2] = f2tff(kv.z); d[3] = f2tff(kv.w);
            float4 vv = *(const float4*)(Vf + (size_t)(bB * S_ + kbase + r) * HID_ + h * 64 + c4 * 4);
            float* d2 = &Vt[r * VSTR + c4 * 4];
            d2[0] = f2tff(vv.x); d2[1] = f2tff(vv.y); d2[2] = f2tff(vv.z); d2[3] = f2tff(vv.w);
        }
        __syncthreads();

        // scores: 16 x 128 tile, warp handles 16 cols (2 n-tiles)
        float c2[2][4] = {};
        #pragma unroll
        for (int ks = 0; ks < 8; ks++) {
            #pragma unroll
            for (int nt = 0; nt < 2; nt++) {
                unsigned bf[2];
                int nb = wid * 16 + nt * 8 + g;
                bf[0] = __float_as_uint(Kt[nb * KSTR + ks * 8 + tg    ]);
                bf[1] = __float_as_uint(Kt[nb * KSTR + ks * 8 + tg + 4]);
                mma8(c2[nt], qa[ks], bf);
            }
        }

        // scale + mask + exp + store P (tf32-rounded) + rowsum partials
        float rs0 = 0.f, rs1 = 0.f;
        #pragma unroll
        for (int nt = 0; nt < 2; nt++) {
            int cb = kbase + wid * 16 + nt * 8 + 2 * tg;
            const int2 mA = *(const int2*)(mask + (size_t)(bB * S_ + s0 + g    ) * S_ + cb);
            const int2 mB = *(const int2*)(mask + (size_t)(bB * S_ + s0 + g + 8) * S_ + cb);
            float v0 = c2[nt][0] * 0.125f; if (mA.x == 0) v0 = -1e10f;
            float v1 = c2[nt][1] * 0.125f; if (mA.y == 0) v1 = -1e10f;
            float v2 = c2[nt][2] * 0.125f; if (mB.x == 0) v2 = -1e10f;
            float v3 = c2[nt][3] * 0.125f; if (mB.y == 0) v3 = -1e10f;
            float p0 = f2tff(__expf(v0));
            float p1 = f2tff(__expf(v1));
            float p2 = f2tff(__expf(v2));
            float p3 = f2tff(__expf(v3));
            P[(g    ) * PSTR + cb    ] = p0;
            P[(g    ) * PSTR + cb + 1] = p1;
            P[(g + 8) * PSTR + cb    ] = p2;
            P[(g + 8) * PSTR + cb + 1] = p3;
            rs0 += p0 + p1;
            rs1 += p2 + p3;
        }
        rs0 += __shfl_xor_sync(0xffffffffu, rs0, 1);
        rs0 += __shfl_xor_sync(0xffffffffu, rs0, 2);
        rs1 += __shfl_xor_sync(0xffffffffu, rs1, 1);
        rs1 += __shfl_xor_sync(0xffffffffu, rs1, 2);
        if ((lane & 3) == 0) {
            atomicAdd(&rowsum[g    ], rs0);
            atomicAdd(&rowsum[g + 8], rs1);
        }
        __syncthreads();   // P tile + rowsum visible

        // PV for this 128-wide k chunk: warp owns 8 output cols
        #pragma unroll
        for (int ks = 0; ks < 16; ks++) {
            unsigned a[4], b[2];
            int kc = kbase + ks * 8;
            a[0] = __float_as_uint(P[(g    ) * PSTR + kc + tg    ]);
            a[1] = __float_as_uint(P[(g + 8) * PSTR + kc + tg    ]);
            a[2] = __float_as_uint(P[(g    ) * PSTR + kc + tg + 4]);
            a[3] = __float_as_uint(P[(g + 8) * PSTR + kc + tg + 4]);
            b[0] = __float_as_uint(Vt[(ks * 8 + tg    ) * VSTR + wid * 8 + g]);
            b[1] = __float_as_uint(Vt[(ks * 8 + tg + 4) * VSTR + wid * 8 + g]);
            mma8(pv, a, b);
        }
        __syncthreads();   // done with Kt/Vt before restage
    }

    if (tid < 16) rowsum[tid] = 1.0f / rowsum[tid];
    __syncthreads();

    // write X (PV normalized), merged-head layout [b, s, 512]
    {
        float i0 = rowsum[g], i1 = rowsum[g + 8];
        int cb = wid * 8 + 2 * tg;
        size_t b0i = (size_t)(bB * S_ + s0 + g    ) * HID_ + h * 64 + cb;
        size_t b1i = (size_t)(bB * S_ + s0 + g + 8) * HID_ + h * 64 + cb;
        Xo[b0i    ] = pv[0] * i0;
        Xo[b0i + 1] = pv[1] * i0;
        Xo[b1i    ] = pv[2] * i1;
        Xo[b1i + 1] = pv[3] * i1;
    }

    // write normalized attn (single pass, coalesced)
    for (int j = 0; j < 128; j++) {
        int lin = j * 256 + tid;
        int r = lin >> 11, c = lin & 2047;
        attn[((size_t)z * S_ + s0 + r) * S_ + c] = P[r * PSTR + c] * rowsum[r];
    }
}

// ---------------------------------------------------------------------------
// Launch
// ---------------------------------------------------------------------------
extern "C" void kernel_launch(void* const* d_in, const int* in_sizes, int n_in,
                              void* d_out, int out_size)
{
    const float* q    = (const float*)d_in[0];
    const float* k    = (const float*)d_in[1];
    const float* v    = (const float*)d_in[2];
    const int*   mask = (const int*)  d_in[3];
    const float* Wq   = (const float*)d_in[4];
    const float* bq   = (const float*)d_in[5];
    const float* Wk   = (const float*)d_in[6];
    const float* bk   = (const float*)d_in[7];
    const float* Wv   = (const float*)d_in[8];
    const float* bv   = (const float*)d_in[9];
    const float* Wo   = (const float*)d_in[10];
    const float* bo   = (const float*)d_in[11];

    float* out = (float*)d_out;

    float *Qf, *Kf, *Vf, *Xf, *scr;
    cudaGetSymbolAddress((void**)&Qf, g_Qh);
    cudaGetSymbolAddress((void**)&Kf, g_Kh);
    cudaGetSymbolAddress((void**)&Vf, g_Vh);
    cudaGetSymbolAddress((void**)&Xf, g_X);
    cudaGetSymbolAddress((void**)&scr, g_attn_scratch);

    const size_t out_elems  = (size_t)M_ * HID_;
    const size_t attn_elems = (size_t)BH_ * S_ * S_;
    float* attn = ((size_t)out_size >= out_elems + attn_elems) ? out + out_elems : scr;

    const int smem_bytes = (16 * PSTR + 128 * KSTR + 128 * VSTR + 16 * KSTR + 16) * 4;
    cudaFuncSetAttribute(attn_fused, cudaFuncAttributeMaxDynamicSharedMemorySize, smem_bytes);

    dim3 gp(8, 32);   // N/64, M/128
    proj_tf32<<<gp, 256>>>(q, Wq, bq, Qf);
    proj_tf32<<<gp, 256>>>(k, Wk, bk, Kf);
    proj_tf32<<<gp, 256>>>(v, Wv, bv, Vf);

    attn_fused<<<dim3(128, 16), 256, smem_bytes>>>(Qf, Kf, Vf, mask, attn, Xf);

    proj_tf32<<<gp, 256>>>(Xf, Wo, bo, out);
}

// round 3
// speedup vs baseline: 2.1335x; 1.3741x over previous
#include <cuda_runtime.h>
#include <math.h>

#define B_    2
#define S_    2048
#define HID_  512
#define H_    8
#define D_    64
#define BH_   16
#define M_    4096

// Scratch (device globals; no allocation allowed)
__device__ float g_Qh[M_ * HID_];
__device__ float g_Kh[M_ * HID_];
__device__ float g_Vh[M_ * HID_];
__device__ float g_X [M_ * HID_];
__device__ float g_rowinv[BH_ * S_];
__device__ float g_attn_scratch[(size_t)BH_ * S_ * S_];

// ---------------------------------------------------------------------------
// tf32 helpers
// ---------------------------------------------------------------------------
__device__ __forceinline__ unsigned f2tf(float x) {
    unsigned u;
    asm("cvt.rna.tf32.f32 %0, %1;" : "=r"(u) : "f"(x));
    return u;
}
__device__ __forceinline__ float f2tff(float x) { return __uint_as_float(f2tf(x)); }

__device__ __forceinline__ void mma8(float c[4], const unsigned a[4], const unsigned b[2]) {
    asm volatile(
        "mma.sync.aligned.m16n8k8.row.col.f32.tf32.tf32.f32 "
        "{%0,%1,%2,%3},{%4,%5,%6,%7},{%8,%9},{%0,%1,%2,%3};"
        : "+f"(c[0]), "+f"(c[1]), "+f"(c[2]), "+f"(c[3])
        : "r"(a[0]), "r"(a[1]), "r"(a[2]), "r"(a[3]),
          "r"(b[0]), "r"(b[1]));
}

// ---------------------------------------------------------------------------
// Projection GEMM (tf32): Y[m][n] = sum_k X[m][k]*W[n][k] + bias[n]
// Block tile 128m x 64n, k-tile 32. 8 warps, warp = 32m x 32n.
// ---------------------------------------------------------------------------
__global__ void __launch_bounds__(256)
proj_tf32(const float* __restrict__ Xg, const float* __restrict__ Wg,
          const float* __restrict__ bias, float* __restrict__ Y)
{
    __shared__ float As[128 * 36];
    __shared__ float Bs[64 * 36];

    const int tid = threadIdx.x;
    const int lane = tid & 31, wid = tid >> 5;
    const int g = lane >> 2, tg = lane & 3;
    const int wm = wid & 3, wn = wid >> 2;
    const int m0 = blockIdx.y * 128, n0 = blockIdx.x * 64;

    float acc[2][4][4] = {};

    for (int k0 = 0; k0 < 512; k0 += 32) {
        #pragma unroll
        for (int jj = 0; jj < 4; jj++) {
            int lin = tid + jj * 256;
            int r = lin >> 3, c4 = lin & 7;
            float4 v = *(const float4*)(Xg + (size_t)(m0 + r) * 512 + k0 + c4 * 4);
            float* d = &As[r * 36 + c4 * 4];
            d[0] = f2tff(v.x); d[1] = f2tff(v.y); d[2] = f2tff(v.z); d[3] = f2tff(v.w);
        }
        #pragma unroll
        for (int jj = 0; jj < 2; jj++) {
            int lin = tid + jj * 256;
            int r = lin >> 3, c4 = lin & 7;
            float4 v = *(const float4*)(Wg + (size_t)(n0 + r) * 512 + k0 + c4 * 4);
            float* d = &Bs[r * 36 + c4 * 4];
            d[0] = f2tff(v.x); d[1] = f2tff(v.y); d[2] = f2tff(v.z); d[3] = f2tff(v.w);
        }
        __syncthreads();

        #pragma unroll
        for (int ks = 0; ks < 4; ks++) {
            unsigned af[2][4], bf[4][2];
            #pragma unroll
            for (int mi = 0; mi < 2; mi++) {
                int rb = wm * 32 + mi * 16;
                af[mi][0] = __float_as_uint(As[(rb + g    ) * 36 + ks * 8 + tg    ]);
                af[mi][1] = __float_as_uint(As[(rb + g + 8) * 36 + ks * 8 + tg    ]);
                af[mi][2] = __float_as_uint(As[(rb + g    ) * 36 + ks * 8 + tg + 4]);
                af[mi][3] = __float_as_uint(As[(rb + g + 8) * 36 + ks * 8 + tg + 4]);
            }
            #pragma unroll
            for (int ni = 0; ni < 4; ni++) {
                int rb = wn * 32 + ni * 8;
                bf[ni][0] = __float_as_uint(Bs[(rb + g) * 36 + ks * 8 + tg    ]);
                bf[ni][1] = __float_as_uint(Bs[(rb + g) * 36 + ks * 8 + tg + 4]);
            }
            #pragma unroll
            for (int mi = 0; mi < 2; mi++)
                #pragma unroll
                for (int ni = 0; ni < 4; ni++)
                    mma8(acc[mi][ni], af[mi], bf[ni]);
        }
        __syncthreads();
    }

    #pragma unroll
    for (int mi = 0; mi < 2; mi++) {
        int r0 = m0 + wm * 32 + mi * 16 + g;
        #pragma unroll
        for (int ni = 0; ni < 4; ni++) {
            int c0 = n0 + wn * 32 + ni * 8 + 2 * tg;
            float b0v = __ldg(bias + c0), b1v = __ldg(bias + c0 + 1);
            Y[(size_t)r0 * 512 + c0    ] = acc[mi][ni][0] + b0v;
            Y[(size_t)r0 * 512 + c0 + 1] = acc[mi][ni][1] + b1v;
            Y[(size_t)(r0 + 8) * 512 + c0    ] = acc[mi][ni][2] + b0v;
            Y[(size_t)(r0 + 8) * 512 + c0 + 1] = acc[mi][ni][3] + b1v;
        }
    }
}

// ---------------------------------------------------------------------------
// Attention pass: 64-row q tile per block, 512 threads (4x4 warps).
// Per 128-col chunk: scores(mma) -> mask -> exp -> write UNNORMALIZED attn
// (coalesced) -> rowsum accumulate -> PV(mma, unnormalized). End: normalize
// PV in regs, store inverse rowsums.
// ---------------------------------------------------------------------------
#define PSTR2 132
#define KSTR  68
#define VSTR  72

__global__ void __launch_bounds__(512)
attn_pass(const float* __restrict__ Qf, const float* __restrict__ Kf,
          const float* __restrict__ Vf, const int* __restrict__ mask,
          float* __restrict__ attn, float* __restrict__ Xo,
          float* __restrict__ rowinv)
{
    extern __shared__ float sm[];
    float* P      = sm;                    // 64 * 132
    float* Kt     = P  + 64 * PSTR2;       // 128 * 68
    float* Vt     = Kt + 128 * KSTR;       // 128 * 72
    float* rowsum = Vt + 128 * VSTR;       // 64

    const int tid = threadIdx.x, lane = tid & 31, wid = tid >> 5;
    const int g = lane >> 2, tg = lane & 3;
    const int wm = wid & 3, wn = wid >> 2;
    const int z = blockIdx.y, strip = blockIdx.x;
    const int bB = z >> 3, h = z & 7;
    const int s0 = strip * 64;

    // stage Q (64x64) into P region, tf32-rounded
    #pragma unroll
    for (int jj = 0; jj < 2; jj++) {
        int lin = tid + jj * 512;
        int r = lin >> 4, c4 = lin & 15;
        float4 v = *(const float4*)(Qf + (size_t)(bB * S_ + s0 + r) * HID_ + h * 64 + c4 * 4);
        float* d = &P[r * PSTR2 + c4 * 4];
        d[0] = f2tff(v.x); d[1] = f2tff(v.y); d[2] = f2tff(v.z); d[3] = f2tff(v.w);
    }
    if (tid < 64) rowsum[tid] = 0.f;
    __syncthreads();

    // persistent Q fragments (rows wm*16 + {g, g+8}, k = head dim 64)
    unsigned qa[8][4];
    #pragma unroll
    for (int ks = 0; ks < 8; ks++) {
        qa[ks][0] = __float_as_uint(P[(wm * 16 + g    ) * PSTR2 + ks * 8 + tg    ]);
        qa[ks][1] = __float_as_uint(P[(wm * 16 + g + 8) * PSTR2 + ks * 8 + tg    ]);
        qa[ks][2] = __float_as_uint(P[(wm * 16 + g    ) * PSTR2 + ks * 8 + tg + 4]);
        qa[ks][3] = __float_as_uint(P[(wm * 16 + g + 8) * PSTR2 + ks * 8 + tg + 4]);
    }

    float pv[2][4] = {};   // warp owns 16 rows x 16 cols of the 64x64 PV output

    for (int it = 0; it < 16; it++) {
        const int kbase = it * 128;

        // stage K,V (128x64 each), tf32-rounded
        #pragma unroll
        for (int jj = 0; jj < 4; jj++) {
            int lin = tid + jj * 512;
            int r = lin >> 4, c4 = lin & 15;
            float4 kv = *(const float4*)(Kf + (size_t)(bB * S_ + kbase + r) * HID_ + h * 64 + c4 * 4);
            float* d = &Kt[r * KSTR + c4 * 4];
            d[0] = f2tff(kv.x); d[1] = f2tff(kv.y); d[2] = f2tff(kv.z); d[3] = f2tff(kv.w);
            float4 vv = *(const float4*)(Vf + (size_t)(bB * S_ + kbase + r) * HID_ + h * 64 + c4 * 4);
            float* d2 = &Vt[r * VSTR + c4 * 4];
            d2[0] = f2tff(vv.x); d2[1] = f2tff(vv.y); d2[2] = f2tff(vv.z); d2[3] = f2tff(vv.w);
        }
        __syncthreads();

        // scores: warp computes 16 rows x 32 cols
        float c2[4][4] = {};
        #pragma unroll
        for (int ks = 0; ks < 8; ks++) {
            #pragma unroll
            for (int nt = 0; nt < 4; nt++) {
                unsigned bf[2];
                int nb = wn * 32 + nt * 8 + g;
                bf[0] = __float_as_uint(Kt[nb * KSTR + ks * 8 + tg    ]);
                bf[1] = __float_as_uint(Kt[nb * KSTR + ks * 8 + tg + 4]);
                mma8(c2[nt], qa[ks], bf);
            }
        }

        // scale + mask + exp -> P chunk (tf32) + rowsum partials
        const int r0 = s0 + wm * 16 + g;
        float rs0 = 0.f, rs1 = 0.f;
        #pragma unroll
        for (int nt = 0; nt < 4; nt++) {
            int cloc = wn * 32 + nt * 8 + 2 * tg;
            int cg = kbase + cloc;
            const int2 mA = *(const int2*)(mask + (size_t)(bB * S_ + r0    ) * S_ + cg);
            const int2 mB = *(const int2*)(mask + (size_t)(bB * S_ + r0 + 8) * S_ + cg);
            float v0 = c2[nt][0] * 0.125f; if (mA.x == 0) v0 = -1e10f;
            float v1 = c2[nt][1] * 0.125f; if (mA.y == 0) v1 = -1e10f;
            float v2 = c2[nt][2] * 0.125f; if (mB.x == 0) v2 = -1e10f;
            float v3 = c2[nt][3] * 0.125f; if (mB.y == 0) v3 = -1e10f;
            float p0 = f2tff(__expf(v0));
            float p1 = f2tff(__expf(v1));
            float p2 = f2tff(__expf(v2));
            float p3 = f2tff(__expf(v3));
            *(float2*)&P[(wm * 16 + g    ) * PSTR2 + cloc] = make_float2(p0, p1);
            *(float2*)&P[(wm * 16 + g + 8) * PSTR2 + cloc] = make_float2(p2, p3);
            rs0 += p0 + p1;
            rs1 += p2 + p3;
        }
        rs0 += __shfl_xor_sync(0xffffffffu, rs0, 1);
        rs0 += __shfl_xor_sync(0xffffffffu, rs0, 2);
        rs1 += __shfl_xor_sync(0xffffffffu, rs1, 1);
        rs1 += __shfl_xor_sync(0xffffffffu, rs1, 2);
        if (tg == 0) {
            atomicAdd(&rowsum[wm * 16 + g    ], rs0);
            atomicAdd(&rowsum[wm * 16 + g + 8], rs1);
        }
        __syncthreads();   // P chunk complete

        // write UNNORMALIZED attn chunk, fully coalesced float4
        #pragma unroll
        for (int jj = 0; jj < 4; jj++) {
            int lin = tid + jj * 512;
            int r = lin >> 5, c4 = lin & 31;
            float4 t = *(const float4*)&P[r * PSTR2 + c4 * 4];
            *(float4*)&attn[((size_t)z * S_ + s0 + r) * S_ + kbase + c4 * 4] = t;
        }

        // PV accumulate: warp owns rows wm*16+{g,g+8}, cols wn*16 + nt*8
        #pragma unroll
        for (int ks = 0; ks < 16; ks++) {
            unsigned a[4];
            int kc = ks * 8;
            a[0] = __float_as_uint(P[(wm * 16 + g    ) * PSTR2 + kc + tg    ]);
            a[1] = __float_as_uint(P[(wm * 16 + g + 8) * PSTR2 + kc + tg    ]);
            a[2] = __float_as_uint(P[(wm * 16 + g    ) * PSTR2 + kc + tg + 4]);
            a[3] = __float_as_uint(P[(wm * 16 + g + 8) * PSTR2 + kc + tg + 4]);
            #pragma unroll
            for (int nt = 0; nt < 2; nt++) {
                unsigned b[2];
                int cb = wn * 16 + nt * 8 + g;
                b[0] = __float_as_uint(Vt[(kc + tg    ) * VSTR + cb]);
                b[1] = __float_as_uint(Vt[(kc + tg + 4) * VSTR + cb]);
                mma8(pv[nt], a, b);
            }
        }
        __syncthreads();   // before restaging K/V, overwriting P
    }

    if (tid < 64) {
        float inv = 1.0f / rowsum[tid];
        rowsum[tid] = inv;
        rowinv[(size_t)z * S_ + s0 + tid] = inv;
    }
    __syncthreads();

    // normalized PV -> X merged-head layout
    {
        float i0 = rowsum[wm * 16 + g], i1 = rowsum[wm * 16 + g + 8];
        #pragma unroll
        for (int nt = 0; nt < 2; nt++) {
            int cb = wn * 16 + nt * 8 + 2 * tg;
            size_t b0i = (size_t)(bB * S_ + s0 + wm * 16 + g    ) * HID_ + h * 64 + cb;
            size_t b1i = (size_t)(bB * S_ + s0 + wm * 16 + g + 8) * HID_ + h * 64 + cb;
            *(float2*)&Xo[b0i] = make_float2(pv[nt][0] * i0, pv[nt][1] * i0);
            *(float2*)&Xo[b1i] = make_float2(pv[nt][2] * i1, pv[nt][3] * i1);
        }
    }
}

// ---------------------------------------------------------------------------
// Normalize attn rows: attn[row, :] *= rowinv[row]. Pure streaming.
// ---------------------------------------------------------------------------
__global__ void __launch_bounds__(256)
norm_pass(float* __restrict__ attn, const float* __restrict__ rowinv)
{
    const size_t row = blockIdx.x;
    const float inv = __ldg(rowinv + row);
    float4* p = (float4*)(attn + row * S_);
    const int t = threadIdx.x;
    #pragma unroll
    for (int i = 0; i < 2; i++) {
        float4 v = p[t + i * 256];
        v.x *= inv; v.y *= inv; v.z *= inv; v.w *= inv;
        p[t + i * 256] = v;
    }
}

// ---------------------------------------------------------------------------
// Launch
// ---------------------------------------------------------------------------
extern "C" void kernel_launch(void* const* d_in, const int* in_sizes, int n_in,
                              void* d_out, int out_size)
{
    const float* q    = (const float*)d_in[0];
    const float* k    = (const float*)d_in[1];
    const float* v    = (const float*)d_in[2];
    const int*   mask = (const int*)  d_in[3];
    const float* Wq   = (const float*)d_in[4];
    const float* bq   = (const float*)d_in[5];
    const float* Wk   = (const float*)d_in[6];
    const float* bk   = (const float*)d_in[7];
    const float* Wv   = (const float*)d_in[8];
    const float* bv   = (const float*)d_in[9];
    const float* Wo   = (const float*)d_in[10];
    const float* bo   = (const float*)d_in[11];

    float* out = (float*)d_out;

    float *Qf, *Kf, *Vf, *Xf, *rinv, *scr;
    cudaGetSymbolAddress((void**)&Qf, g_Qh);
    cudaGetSymbolAddress((void**)&Kf, g_Kh);
    cudaGetSymbolAddress((void**)&Vf, g_Vh);
    cudaGetSymbolAddress((void**)&Xf, g_X);
    cudaGetSymbolAddress((void**)&rinv, g_rowinv);
    cudaGetSymbolAddress((void**)&scr, g_attn_scratch);

    const size_t out_elems  = (size_t)M_ * HID_;
    const size_t attn_elems = (size_t)BH_ * S_ * S_;
    float* attn = ((size_t)out_size >= out_elems + attn_elems) ? out + out_elems : scr;

    const int smem_bytes = (64 * PSTR2 + 128 * KSTR + 128 * VSTR + 64) * 4;
    cudaFuncSetAttribute(attn_pass, cudaFuncAttributeMaxDynamicSharedMemorySize, smem_bytes);

    dim3 gp(8, 32);
    proj_tf32<<<gp, 256>>>(q, Wq, bq, Qf);
    proj_tf32<<<gp, 256>>>(k, Wk, bk, Kf);
    proj_tf32<<<gp, 256>>>(v, Wv, bv, Vf);

    attn_pass<<<dim3(32, 16), 512, smem_bytes>>>(Qf, Kf, Vf, mask, attn, Xf, rinv);

    proj_tf32<<<gp, 256>>>(Xf, Wo, bo, out);

    norm_pass<<<(unsigned)(BH_ * S_), 256>>>(attn, rinv);
}

// round 4
// speedup vs baseline: 2.3162x; 1.0856x over previous
#include <cuda_runtime.h>
#include <math.h>

#define B_    2
#define S_    2048
#define HID_  512
#define H_    8
#define D_    64
#define BH_   16
#define M_    4096

// Scratch (device globals; no allocation allowed)
__device__ float g_Qh[M_ * HID_];
__device__ float g_Kh[M_ * HID_];
__device__ float g_Vh[M_ * HID_];
__device__ float g_X [M_ * HID_];
__device__ float g_attn_scratch[(size_t)BH_ * S_ * S_];

// ---------------------------------------------------------------------------
// helpers
// ---------------------------------------------------------------------------
__device__ __forceinline__ unsigned f2tf(float x) {
    unsigned u;
    asm("cvt.rna.tf32.f32 %0, %1;" : "=r"(u) : "f"(x));
    return u;
}
__device__ __forceinline__ float f2tff(float x) { return __uint_as_float(f2tf(x)); }

__device__ __forceinline__ void mma8(float c[4], const unsigned a[4], const unsigned b[2]) {
    asm volatile(
        "mma.sync.aligned.m16n8k8.row.col.f32.tf32.tf32.f32 "
        "{%0,%1,%2,%3},{%4,%5,%6,%7},{%8,%9},{%0,%1,%2,%3};"
        : "+f"(c[0]), "+f"(c[1]), "+f"(c[2]), "+f"(c[3])
        : "r"(a[0]), "r"(a[1]), "r"(a[2]), "r"(a[3]),
          "r"(b[0]), "r"(b[1]));
}

__device__ __forceinline__ unsigned sptr(const void* p) {
    return (unsigned)__cvta_generic_to_shared(p);
}
__device__ __forceinline__ void cp16(unsigned saddr, const void* g) {
    asm volatile("cp.async.cg.shared.global [%0], [%1], 16;" :: "r"(saddr), "l"(g));
}

// ---------------------------------------------------------------------------
// Projection GEMM (tf32): Y[m][n] = sum_k X[m][k]*W[n][k] + bias[n]
// Block tile 128m x 64n, k-tile 32. 8 warps. Up to 3 problems per launch
// selected by blockIdx.z (merged Q/K/V projections).
// ---------------------------------------------------------------------------
struct ProjArgs { const float *X, *W, *b; float *Y; };

__global__ void __launch_bounds__(256)
proj_tf32(ProjArgs a0, ProjArgs a1, ProjArgs a2)
{
    const ProjArgs& A_ = (blockIdx.z == 0) ? a0 : (blockIdx.z == 1) ? a1 : a2;
    const float* __restrict__ Xg = A_.X;
    const float* __restrict__ Wg = A_.W;
    const float* __restrict__ bias = A_.b;
    float* __restrict__ Y = A_.Y;

    __shared__ float As[128 * 36];
    __shared__ float Bs[64 * 36];

    const int tid = threadIdx.x;
    const int lane = tid & 31, wid = tid >> 5;
    const int g = lane >> 2, tg = lane & 3;
    const int wm = wid & 3, wn = wid >> 2;
    const int m0 = blockIdx.y * 128, n0 = blockIdx.x * 64;

    float acc[2][4][4] = {};

    for (int k0 = 0; k0 < 512; k0 += 32) {
        #pragma unroll
        for (int jj = 0; jj < 4; jj++) {
            int lin = tid + jj * 256;
            int r = lin >> 3, c4 = lin & 7;
            float4 v = *(const float4*)(Xg + (size_t)(m0 + r) * 512 + k0 + c4 * 4);
            float* d = &As[r * 36 + c4 * 4];
            d[0] = f2tff(v.x); d[1] = f2tff(v.y); d[2] = f2tff(v.z); d[3] = f2tff(v.w);
        }
        #pragma unroll
        for (int jj = 0; jj < 2; jj++) {
            int lin = tid + jj * 256;
            int r = lin >> 3, c4 = lin & 7;
            float4 v = *(const float4*)(Wg + (size_t)(n0 + r) * 512 + k0 + c4 * 4);
            float* d = &Bs[r * 36 + c4 * 4];
            d[0] = f2tff(v.x); d[1] = f2tff(v.y); d[2] = f2tff(v.z); d[3] = f2tff(v.w);
        }
        __syncthreads();

        #pragma unroll
        for (int ks = 0; ks < 4; ks++) {
            unsigned af[2][4], bf[4][2];
            #pragma unroll
            for (int mi = 0; mi < 2; mi++) {
                int rb = wm * 32 + mi * 16;
                af[mi][0] = __float_as_uint(As[(rb + g    ) * 36 + ks * 8 + tg    ]);
                af[mi][1] = __float_as_uint(As[(rb + g + 8) * 36 + ks * 8 + tg    ]);
                af[mi][2] = __float_as_uint(As[(rb + g    ) * 36 + ks * 8 + tg + 4]);
                af[mi][3] = __float_as_uint(As[(rb + g + 8) * 36 + ks * 8 + tg + 4]);
            }
            #pragma unroll
            for (int ni = 0; ni < 4; ni++) {
                int rb = wn * 32 + ni * 8;
                bf[ni][0] = __float_as_uint(Bs[(rb + g) * 36 + ks * 8 + tg    ]);
                bf[ni][1] = __float_as_uint(Bs[(rb + g) * 36 + ks * 8 + tg + 4]);
            }
            #pragma unroll
            for (int mi = 0; mi < 2; mi++)
                #pragma unroll
                for (int ni = 0; ni < 4; ni++)
                    mma8(acc[mi][ni], af[mi], bf[ni]);
        }
        __syncthreads();
    }

    #pragma unroll
    for (int mi = 0; mi < 2; mi++) {
        int r0 = m0 + wm * 32 + mi * 16 + g;
        #pragma unroll
        for (int ni = 0; ni < 4; ni++) {
            int c0 = n0 + wn * 32 + ni * 8 + 2 * tg;
            float b0v = __ldg(bias + c0), b1v = __ldg(bias + c0 + 1);
            Y[(size_t)r0 * 512 + c0    ] = acc[mi][ni][0] + b0v;
            Y[(size_t)r0 * 512 + c0 + 1] = acc[mi][ni][1] + b1v;
            Y[(size_t)(r0 + 8) * 512 + c0    ] = acc[mi][ni][2] + b0v;
            Y[(size_t)(r0 + 8) * 512 + c0 + 1] = acc[mi][ni][3] + b1v;
        }
    }
}

// ---------------------------------------------------------------------------
// Fused attention: 64-row q tile per block, 512 threads (4x4 warps).
// cp.async double-buffered K/V (raw fp32; tf32 cvt at fragment build).
// Per chunk: mask prefetch -> scores mma -> exp -> unnormalized attn write
// + rowsum -> PV mma. Tail: normalize PV, rescale own attn slab in gmem.
// ---------------------------------------------------------------------------
#define PSTR2 132
#define KSTR  68
#define VSTR  72

__global__ void __launch_bounds__(512, 1)
attn_pass(const float* __restrict__ Qf, const float* __restrict__ Kf,
          const float* __restrict__ Vf, const int* __restrict__ mask,
          float* __restrict__ attn, float* __restrict__ Xo)
{
    extern __shared__ float sm[];
    float* P      = sm;                        // 64 * 132
    float* Kb[2]  = { P + 64 * PSTR2, P + 64 * PSTR2 + 128 * KSTR };
    float* Vb[2]  = { Kb[1] + 128 * KSTR, Kb[1] + 128 * KSTR + 128 * VSTR };
    float* rowsum = Vb[1] + 128 * VSTR;        // 64

    const int tid = threadIdx.x, lane = tid & 31, wid = tid >> 5;
    const int g = lane >> 2, tg = lane & 3;
    const int wm = wid & 3, wn = wid >> 2;
    const int z = blockIdx.y, strip = blockIdx.x;
    const int bB = z >> 3, h = z & 7;
    const int s0 = strip * 64;

    // prologue: async-load chunk 0
    {
        #pragma unroll
        for (int jj = 0; jj < 4; jj++) {
            int lin = tid + jj * 512;
            int r = lin >> 4, c4 = lin & 15;
            size_t grow = (size_t)(bB * S_ + r) * HID_ + h * 64 + c4 * 4;
            cp16(sptr(Kb[0] + r * KSTR + c4 * 4), Kf + grow);
            cp16(sptr(Vb[0] + r * VSTR + c4 * 4), Vf + grow);
        }
        asm volatile("cp.async.commit_group;");
    }

    // stage Q (64x64) into P region, tf32-rounded
    #pragma unroll
    for (int jj = 0; jj < 2; jj++) {
        int lin = tid + jj * 512;
        int r = lin >> 4, c4 = lin & 15;
        float4 v = *(const float4*)(Qf + (size_t)(bB * S_ + s0 + r) * HID_ + h * 64 + c4 * 4);
        float* d = &P[r * PSTR2 + c4 * 4];
        d[0] = f2tff(v.x); d[1] = f2tff(v.y); d[2] = f2tff(v.z); d[3] = f2tff(v.w);
    }
    if (tid < 64) rowsum[tid] = 0.f;
    __syncthreads();

    // persistent Q fragments
    unsigned qa[8][4];
    #pragma unroll
    for (int ks = 0; ks < 8; ks++) {
        qa[ks][0] = __float_as_uint(P[(wm * 16 + g    ) * PSTR2 + ks * 8 + tg    ]);
        qa[ks][1] = __float_as_uint(P[(wm * 16 + g + 8) * PSTR2 + ks * 8 + tg    ]);
        qa[ks][2] = __float_as_uint(P[(wm * 16 + g    ) * PSTR2 + ks * 8 + tg + 4]);
        qa[ks][3] = __float_as_uint(P[(wm * 16 + g + 8) * PSTR2 + ks * 8 + tg + 4]);
    }

    float pv[2][4] = {};
    const int r0g = s0 + wm * 16 + g;   // global row (within batch seq) for this thread

    for (int it = 0; it < 16; it++) {
        const int kbase = it * 128;
        const int cur = it & 1;

        // issue async loads for next chunk (other buffer)
        if (it < 15) {
            const int nb = kbase + 128;
            #pragma unroll
            for (int jj = 0; jj < 4; jj++) {
                int lin = tid + jj * 512;
                int r = lin >> 4, c4 = lin & 15;
                size_t grow = (size_t)(bB * S_ + nb + r) * HID_ + h * 64 + c4 * 4;
                cp16(sptr(Kb[cur ^ 1] + r * KSTR + c4 * 4), Kf + grow);
                cp16(sptr(Vb[cur ^ 1] + r * VSTR + c4 * 4), Vf + grow);
            }
            asm volatile("cp.async.commit_group;");
        }

        // prefetch mask into regs (consumed after scores mma)
        int2 mA[4], mB[4];
        #pragma unroll
        for (int nt = 0; nt < 4; nt++) {
            int cg = kbase + wn * 32 + nt * 8 + 2 * tg;
            mA[nt] = *(const int2*)(mask + (size_t)(bB * S_ + r0g    ) * S_ + cg);
            mB[nt] = *(const int2*)(mask + (size_t)(bB * S_ + r0g + 8) * S_ + cg);
        }

        // wait for current chunk's K/V
        if (it < 15) asm volatile("cp.async.wait_group 1;");
        else         asm volatile("cp.async.wait_group 0;");
        __syncthreads();

        const float* Kt = Kb[cur];
        const float* Vt = Vb[cur];

        // scores: warp computes 16 rows x 32 cols (cvt K frags here)
        float c2[4][4] = {};
        #pragma unroll
        for (int ks = 0; ks < 8; ks++) {
            #pragma unroll
            for (int nt = 0; nt < 4; nt++) {
                unsigned bf[2];
                int nb2 = wn * 32 + nt * 8 + g;
                bf[0] = f2tf(Kt[nb2 * KSTR + ks * 8 + tg    ]);
                bf[1] = f2tf(Kt[nb2 * KSTR + ks * 8 + tg + 4]);
                mma8(c2[nt], qa[ks], bf);
            }
        }

        // scale + mask + exp -> P chunk (tf32) + rowsum partials
        float rs0 = 0.f, rs1 = 0.f;
        #pragma unroll
        for (int nt = 0; nt < 4; nt++) {
            int cloc = wn * 32 + nt * 8 + 2 * tg;
            float v0 = c2[nt][0] * 0.125f; if (mA[nt].x == 0) v0 = -1e10f;
            float v1 = c2[nt][1] * 0.125f; if (mA[nt].y == 0) v1 = -1e10f;
            float v2 = c2[nt][2] * 0.125f; if (mB[nt].x == 0) v2 = -1e10f;
            float v3 = c2[nt][3] * 0.125f; if (mB[nt].y == 0) v3 = -1e10f;
            float p0 = f2tff(__expf(v0));
            float p1 = f2tff(__expf(v1));
            float p2 = f2tff(__expf(v2));
            float p3 = f2tff(__expf(v3));
            *(float2*)&P[(wm * 16 + g    ) * PSTR2 + cloc] = make_float2(p0, p1);
            *(float2*)&P[(wm * 16 + g + 8) * PSTR2 + cloc] = make_float2(p2, p3);
            rs0 += p0 + p1;
            rs1 += p2 + p3;
        }
        rs0 += __shfl_xor_sync(0xffffffffu, rs0, 1);
        rs0 += __shfl_xor_sync(0xffffffffu, rs0, 2);
        rs1 += __shfl_xor_sync(0xffffffffu, rs1, 1);
        rs1 += __shfl_xor_sync(0xffffffffu, rs1, 2);
        if (tg == 0) {
            atomicAdd(&rowsum[wm * 16 + g    ], rs0);
            atomicAdd(&rowsum[wm * 16 + g + 8], rs1);
        }
        __syncthreads();   // P chunk complete

        // write UNNORMALIZED attn chunk (coalesced float4)
        #pragma unroll
        for (int jj = 0; jj < 4; jj++) {
            int lin = tid + jj * 512;
            int r = lin >> 5, c4 = lin & 31;
            float4 t = *(const float4*)&P[r * PSTR2 + c4 * 4];
            *(float4*)&attn[((size_t)z * S_ + s0 + r) * S_ + kbase + c4 * 4] = t;
        }

        // PV accumulate (cvt V frags here)
        #pragma unroll
        for (int ks = 0; ks < 16; ks++) {
            unsigned a[4];
            int kc = ks * 8;
            a[0] = __float_as_uint(P[(wm * 16 + g    ) * PSTR2 + kc + tg    ]);
            a[1] = __float_as_uint(P[(wm * 16 + g + 8) * PSTR2 + kc + tg    ]);
            a[2] = __float_as_uint(P[(wm * 16 + g    ) * PSTR2 + kc + tg + 4]);
            a[3] = __float_as_uint(P[(wm * 16 + g + 8) * PSTR2 + kc + tg + 4]);
            #pragma unroll
            for (int nt = 0; nt < 2; nt++) {
                unsigned b[2];
                int cb = wn * 16 + nt * 8 + g;
                b[0] = f2tf(Vt[(kc + tg    ) * VSTR + cb]);
                b[1] = f2tf(Vt[(kc + tg + 4) * VSTR + cb]);
                mma8(pv[nt], a, b);
            }
        }
        __syncthreads();   // done with buffers + P before next chunk
    }

    if (tid < 64) rowsum[tid] = 1.0f / rowsum[tid];
    __syncthreads();

    // normalized PV -> X merged-head layout
    {
        float i0 = rowsum[wm * 16 + g], i1 = rowsum[wm * 16 + g + 8];
        #pragma unroll
        for (int nt = 0; nt < 2; nt++) {
            int cb = wn * 16 + nt * 8 + 2 * tg;
            size_t b0i = (size_t)(bB * S_ + s0 + wm * 16 + g    ) * HID_ + h * 64 + cb;
            size_t b1i = (size_t)(bB * S_ + s0 + wm * 16 + g + 8) * HID_ + h * 64 + cb;
            *(float2*)&Xo[b0i] = make_float2(pv[nt][0] * i0, pv[nt][1] * i0);
            *(float2*)&Xo[b1i] = make_float2(pv[nt][2] * i1, pv[nt][3] * i1);
        }
    }

    // fused normalization: rescale this block's 64x2048 attn slab
    float4* slab = (float4*)(attn + ((size_t)z * S_ + s0) * S_);
    #pragma unroll 4
    for (int jj = 0; jj < 64; jj++) {
        int lin = jj * 512 + tid;
        int r = lin >> 9, c4 = lin & 511;
        float inv = rowsum[r];
        float4 t = slab[(size_t)r * 512 + c4];
        t.x *= inv; t.y *= inv; t.z *= inv; t.w *= inv;
        slab[(size_t)r * 512 + c4] = t;
    }
}

// ---------------------------------------------------------------------------
// Launch
// ---------------------------------------------------------------------------
extern "C" void kernel_launch(void* const* d_in, const int* in_sizes, int n_in,
                              void* d_out, int out_size)
{
    const float* q    = (const float*)d_in[0];
    const float* k    = (const float*)d_in[1];
    const float* v    = (const float*)d_in[2];
    const int*   mask = (const int*)  d_in[3];
    const float* Wq   = (const float*)d_in[4];
    const float* bq   = (const float*)d_in[5];
    const float* Wk   = (const float*)d_in[6];
    const float* bk   = (const float*)d_in[7];
    const float* Wv   = (const float*)d_in[8];
    const float* bv   = (const float*)d_in[9];
    const float* Wo   = (const float*)d_in[10];
    const float* bo   = (const float*)d_in[11];

    float* out = (float*)d_out;

    float *Qf, *Kf, *Vf, *Xf, *scr;
    cudaGetSymbolAddress((void**)&Qf, g_Qh);
    cudaGetSymbolAddress((void**)&Kf, g_Kh);
    cudaGetSymbolAddress((void**)&Vf, g_Vh);
    cudaGetSymbolAddress((void**)&Xf, g_X);
    cudaGetSymbolAddress((void**)&scr, g_attn_scratch);

    const size_t out_elems  = (size_t)M_ * HID_;
    const size_t attn_elems = (size_t)BH_ * S_ * S_;
    float* attn = ((size_t)out_size >= out_elems + attn_elems) ? out + out_elems : scr;

    const int smem_bytes = (64 * PSTR2 + 2 * 128 * KSTR + 2 * 128 * VSTR + 64) * 4;
    cudaFuncSetAttribute(attn_pass, cudaFuncAttributeMaxDynamicSharedMemorySize, smem_bytes);

    // merged Q/K/V projections
    ProjArgs pq{q, Wq, bq, Qf}, pk{k, Wk, bk, Kf}, pvv{v, Wv, bv, Vf};
    proj_tf32<<<dim3(8, 32, 3), 256>>>(pq, pk, pvv);

    attn_pass<<<dim3(32, 16), 512, smem_bytes>>>(Qf, Kf, Vf, mask, attn, Xf);

    ProjArgs po{Xf, Wo, bo, out};
    proj_tf32<<<dim3(8, 32, 1), 256>>>(po, po, po);
}

// round 6
// speedup vs baseline: 2.8230x; 1.2188x over previous
#include <cuda_runtime.h>
#include <cuda_fp16.h>
#include <math.h>
#include <stdint.h>

#define B_    2
#define S_    2048
#define HID_  512
#define H_    8
#define BH_   16
#define M_    4096

// Scratch (device globals; no allocation allowed)
__device__ __align__(256) __half g_Qh[M_ * HID_];
__device__ __align__(256) __half g_Kh[M_ * HID_];
__device__ __align__(256) __half g_Vh[M_ * HID_];
__device__ __align__(256) __half g_Vt[BH_ * 64 * S_];   // [z][d][s]
__device__ float g_X [M_ * HID_];
__device__ float g_attn_scratch[(size_t)BH_ * S_ * S_];

// ---------------------------------------------------------------------------
// helpers
// ---------------------------------------------------------------------------
__device__ __forceinline__ unsigned f2tf(float x) {
    unsigned u;
    asm("cvt.rna.tf32.f32 %0, %1;" : "=r"(u) : "f"(x));
    return u;
}
__device__ __forceinline__ float f2tff(float x) { return __uint_as_float(f2tf(x)); }

// tf32 k8 mma (projections)
__device__ __forceinline__ void mma8(float c[4], const unsigned a[4], const unsigned b[2]) {
    asm volatile(
        "mma.sync.aligned.m16n8k8.row.col.f32.tf32.tf32.f32 "
        "{%0,%1,%2,%3},{%4,%5,%6,%7},{%8,%9},{%0,%1,%2,%3};"
        : "+f"(c[0]), "+f"(c[1]), "+f"(c[2]), "+f"(c[3])
        : "r"(a[0]), "r"(a[1]), "r"(a[2]), "r"(a[3]),
          "r"(b[0]), "r"(b[1]));
}

// fp16 k16 mma (attention)
__device__ __forceinline__ void mmah(float c[4], const unsigned a[4], const unsigned b[2]) {
    asm volatile(
        "mma.sync.aligned.m16n8k16.row.col.f32.f16.f16.f32 "
        "{%0,%1,%2,%3},{%4,%5,%6,%7},{%8,%9},{%0,%1,%2,%3};"
        : "+f"(c[0]), "+f"(c[1]), "+f"(c[2]), "+f"(c[3])
        : "r"(a[0]), "r"(a[1]), "r"(a[2]), "r"(a[3]),
          "r"(b[0]), "r"(b[1]));
}

__device__ __forceinline__ void cp16(uint32_t saddr, const void* g) {
    asm volatile("cp.async.cg.shared.global [%0], [%1], 16;" :: "r"(saddr), "l"(g));
}
__device__ __forceinline__ uint32_t sptr(const void* p) {
    return (uint32_t)__cvta_generic_to_shared(p);
}

// ---------------------------------------------------------------------------
// Projection GEMM (tf32 mma.sync): Y = X @ W^T + b.
// Writes float (Yf) or half (Yh, with pre-scale).
// ---------------------------------------------------------------------------
struct ProjArgs { const float *X, *W, *b; float *Yf; __half *Yh; float scale; };

__global__ void __launch_bounds__(256)
proj_tf32(ProjArgs a0, ProjArgs a1, ProjArgs a2)
{
    const ProjArgs& A_ = (blockIdx.z == 0) ? a0 : (blockIdx.z == 1) ? a1 : a2;
    const float* __restrict__ Xg = A_.X;
    const float* __restrict__ Wg = A_.W;
    const float* __restrict__ bias = A_.b;

    __shared__ float As[128 * 36];
    __shared__ float Bs[64 * 36];

    const int tid = threadIdx.x;
    const int lane = tid & 31, wid = tid >> 5;
    const int g = lane >> 2, tg = lane & 3;
    const int wm = wid & 3, wn = wid >> 2;
    const int m0 = blockIdx.y * 128, n0 = blockIdx.x * 64;

    float acc[2][4][4] = {};

    for (int k0 = 0; k0 < 512; k0 += 32) {
        #pragma unroll
        for (int jj = 0; jj < 4; jj++) {
            int lin = tid + jj * 256;
            int r = lin >> 3, c4 = lin & 7;
            float4 v = *(const float4*)(Xg + (size_t)(m0 + r) * 512 + k0 + c4 * 4);
            float* d = &As[r * 36 + c4 * 4];
            d[0] = f2tff(v.x); d[1] = f2tff(v.y); d[2] = f2tff(v.z); d[3] = f2tff(v.w);
        }
        #pragma unroll
        for (int jj = 0; jj < 2; jj++) {
            int lin = tid + jj * 256;
            int r = lin >> 3, c4 = lin & 7;
            float4 v = *(const float4*)(Wg + (size_t)(n0 + r) * 512 + k0 + c4 * 4);
            float* d = &Bs[r * 36 + c4 * 4];
            d[0] = f2tff(v.x); d[1] = f2tff(v.y); d[2] = f2tff(v.z); d[3] = f2tff(v.w);
        }
        __syncthreads();

        #pragma unroll
        for (int ks = 0; ks < 4; ks++) {
            unsigned af[2][4], bf[4][2];
            #pragma unroll
            for (int mi = 0; mi < 2; mi++) {
                int rb = wm * 32 + mi * 16;
                af[mi][0] = __float_as_uint(As[(rb + g    ) * 36 + ks * 8 + tg    ]);
                af[mi][1] = __float_as_uint(As[(rb + g + 8) * 36 + ks * 8 + tg    ]);
                af[mi][2] = __float_as_uint(As[(rb + g    ) * 36 + ks * 8 + tg + 4]);
                af[mi][3] = __float_as_uint(As[(rb + g + 8) * 36 + ks * 8 + tg + 4]);
            }
            #pragma unroll
            for (int ni = 0; ni < 4; ni++) {
                int rb = wn * 32 + ni * 8;
                bf[ni][0] = __float_as_uint(Bs[(rb + g) * 36 + ks * 8 + tg    ]);
                bf[ni][1] = __float_as_uint(Bs[(rb + g) * 36 + ks * 8 + tg + 4]);
            }
            #pragma unroll
            for (int mi = 0; mi < 2; mi++)
                #pragma unroll
                for (int ni = 0; ni < 4; ni++)
                    mma8(acc[mi][ni], af[mi], bf[ni]);
        }
        __syncthreads();
    }

    const float scale = A_.scale;
    #pragma unroll
    for (int mi = 0; mi < 2; mi++) {
        int r0 = m0 + wm * 32 + mi * 16 + g;
        #pragma unroll
        for (int ni = 0; ni < 4; ni++) {
            int c0 = n0 + wn * 32 + ni * 8 + 2 * tg;
            float b0v = __ldg(bias + c0), b1v = __ldg(bias + c0 + 1);
            float y00 = acc[mi][ni][0] + b0v, y01 = acc[mi][ni][1] + b1v;
            float y10 = acc[mi][ni][2] + b0v, y11 = acc[mi][ni][3] + b1v;
            if (A_.Yh) {
                A_.Yh[(size_t)r0 * 512 + c0    ] = __float2half_rn(y00 * scale);
                A_.Yh[(size_t)r0 * 512 + c0 + 1] = __float2half_rn(y01 * scale);
                A_.Yh[(size_t)(r0 + 8) * 512 + c0    ] = __float2half_rn(y10 * scale);
                A_.Yh[(size_t)(r0 + 8) * 512 + c0 + 1] = __float2half_rn(y11 * scale);
            } else {
                A_.Yf[(size_t)r0 * 512 + c0    ] = y00;
                A_.Yf[(size_t)r0 * 512 + c0 + 1] = y01;
                A_.Yf[(size_t)(r0 + 8) * 512 + c0    ] = y10;
                A_.Yf[(size_t)(r0 + 8) * 512 + c0 + 1] = y11;
            }
        }
    }
}

// ---------------------------------------------------------------------------
// V transpose: Vh [b, s, hid] (half) -> Vt [z=b*8+h][d][s] (half)
// ---------------------------------------------------------------------------
__global__ void __launch_bounds__(256)
vtrans(const __half* __restrict__ Vh, __half* __restrict__ Vt)
{
    __shared__ __half ts[64 * 72];
    const int tid = threadIdx.x;
    const int z = blockIdx.y, bB = z >> 3, h = z & 7;
    const int s0 = blockIdx.x * 64;

    #pragma unroll
    for (int j = 0; j < 8; j++) {
        int lin = tid + j * 256;
        int s = lin >> 5, du = lin & 31;
        *(uint32_t*)(ts + s * 72 + du * 2) =
            *(const uint32_t*)(Vh + (size_t)(bB * S_ + s0 + s) * HID_ + h * 64 + du * 2);
    }
    __syncthreads();
    #pragma unroll
    for (int j = 0; j < 8; j++) {
        int lin = tid + j * 256;
        int d = lin >> 5, su = lin & 31;
        __half2 o = __halves2half2(ts[(2 * su) * 72 + d], ts[(2 * su + 1) * 72 + d]);
        *(__half2*)(Vt + ((size_t)z * 64 + d) * S_ + s0 + su * 2) = o;
    }
}

// ---------------------------------------------------------------------------
// FA2-style fused attention (fp16 mma, register-resident P).
// Block: 512 thr (16 warps: wm=w&3 rows, wn=w>>2 k-slices), q-tile 64 rows,
// 16 chunks x 128 k-cols, 3-stage cp.async ring, 1 barrier per chunk.
// SMEM (bytes from base):
//   Q   @0      64x72h   9216
//   K s @9216 + s*18432  (128x72h each)        ... 3 stages
//   Vt s @64512 + s*17408 (64x136h each)       ... 3 stages
//   rows @116736 64 f32
// Scratch for PV reduction reuses K/Vt region (64KB) at @9216.
// ---------------------------------------------------------------------------
#define SMB_Q    0u
#define SMB_K(s) (9216u + (s) * 18432u)
#define SMB_V(s) (64512u + (s) * 17408u)
#define SMB_RS   116736u
#define ATTN_SMEM (117008 + 16)

__global__ void __launch_bounds__(512, 1)
attn_fa(const __half* __restrict__ Qh, const __half* __restrict__ Kh,
        const __half* __restrict__ Vtg, const int* __restrict__ mask,
        float* __restrict__ attn, float* __restrict__ Xo)
{
    extern __shared__ char smg[];
    const uint32_t sb = sptr(smg);

    const int tid = threadIdx.x, lane = tid & 31, w = tid >> 5;
    const int g = lane >> 2, tg = lane & 3;
    const int wm = w & 3, wn = w >> 2;
    const int z = blockIdx.y, strip = blockIdx.x;
    const int bB = z >> 3, h = z & 7;
    const int s0 = strip * 64;

    float* rows = (float*)(smg + SMB_RS);
    if (tid < 64) rows[tid] = 0.f;

    const __half* Qsrc = Qh + (size_t)(bB * S_ + s0) * HID_ + h * 64;
    const __half* Ksrc = Kh + (size_t)(bB * S_) * HID_ + h * 64;
    const __half* Vsrc = Vtg + (size_t)z * 64 * S_;

    // stage loaders
    auto loadK = [&](int chunk, int st) {
        const int kb = chunk * 128;
        #pragma unroll
        for (int j = 0; j < 2; j++) {
            int idx = tid + j * 512;
            int r = idx >> 3, c16 = idx & 7;
            cp16(sb + SMB_K(st) + (uint32_t)r * 144u + (uint32_t)c16 * 16u,
                 Ksrc + (size_t)(kb + r) * HID_ + c16 * 8);
        }
        #pragma unroll
        for (int j = 0; j < 2; j++) {
            int idx = tid + j * 512;
            int d = idx >> 4, c16 = idx & 15;
            cp16(sb + SMB_V(st) + (uint32_t)d * 272u + (uint32_t)c16 * 16u,
                 Vsrc + (size_t)d * S_ + kb + c16 * 8);
        }
    };

    // prologue: Q + chunk0 (group0), chunk1 (group1)
    {
        int r = tid >> 3, c16 = tid & 7;
        cp16(sb + SMB_Q + (uint32_t)r * 144u + (uint32_t)c16 * 16u,
             Qsrc + (size_t)r * HID_ + c16 * 8);
    }
    loadK(0, 0);
    asm volatile("cp.async.commit_group;");
    loadK(1, 1);
    asm volatile("cp.async.commit_group;");

    // wait group0 (Q + chunk0) before reading Q frags
    asm volatile("cp.async.wait_group 1;");
    __syncthreads();

    const __half* Qs = (const __half*)(smg + SMB_Q);
    unsigned qa[4][4];
    #pragma unroll
    for (int ks = 0; ks < 4; ks++) {
        const __half* qr0 = Qs + (wm * 16 + g) * 72 + ks * 16 + 2 * tg;
        const __half* qr1 = qr0 + 8 * 72;
        qa[ks][0] = *(const uint32_t*)qr0;
        qa[ks][1] = *(const uint32_t*)qr1;
        qa[ks][2] = *(const uint32_t*)(qr0 + 8);
        qa[ks][3] = *(const uint32_t*)(qr1 + 8);
    }

    float pvacc[8][4] = {};
    float rsA = 0.f, rsB = 0.f;   // rowsum partials for rows g, g+8

    const int rA = bB * S_ + s0 + wm * 16 + g;      // mask row A
    const size_t arowA = ((size_t)z * S_ + s0 + wm * 16 + g) * S_;
    const size_t arowB = arowA + 8 * S_;

    for (int it = 0; it < 16; it++) {
        const int kb = it * 128;
        const int st = it % 3;

        // mask prefetch (independent of smem): rows g,g+8, 4 ntiles
        int2 mA[4], mB[4];
        #pragma unroll
        for (int nt = 0; nt < 4; nt++) {
            int cg = kb + wn * 32 + nt * 8 + 2 * tg;
            mA[nt] = __ldg((const int2*)(mask + (size_t)rA * S_ + cg));
            mB[nt] = __ldg((const int2*)(mask + (size_t)(rA + 8) * S_ + cg));
        }

        if (it > 0) {  // it==0 already waited above
            if (it < 15) asm volatile("cp.async.wait_group 1;");
            else         asm volatile("cp.async.wait_group 0;");
            __syncthreads();
        }

        // prefetch chunk it+2 into stage (it+2)%3 (consumed at it-1, safe now)
        if (it + 2 < 16) {
            loadK(it + 2, (it + 2) % 3);
            asm volatile("cp.async.commit_group;");
        }

        const __half* Ks = (const __half*)(smg + SMB_K(st));
        const __half* Vs = (const __half*)(smg + SMB_V(st));

        // scores: warp = 16 rows x 32 cols (4 ntiles), k=64 via 4 k16 steps
        float c[4][4] = {};
        #pragma unroll
        for (int ks = 0; ks < 4; ks++) {
            #pragma unroll
            for (int nt = 0; nt < 4; nt++) {
                const __half* kp = Ks + (wn * 32 + nt * 8 + g) * 72 + ks * 16 + 2 * tg;
                unsigned b[2];
                b[0] = *(const uint32_t*)kp;
                b[1] = *(const uint32_t*)(kp + 8);
                mmah(c[nt], qa[ks], b);
            }
        }

        // mask + exp (scale folded into Q), attn write, P->half2 A frags
        float p[4][4];
        #pragma unroll
        for (int nt = 0; nt < 4; nt++) {
            p[nt][0] = (mA[nt].x != 0) ? __expf(c[nt][0]) : 0.f;
            p[nt][1] = (mA[nt].y != 0) ? __expf(c[nt][1]) : 0.f;
            p[nt][2] = (mB[nt].x != 0) ? __expf(c[nt][2]) : 0.f;
            p[nt][3] = (mB[nt].y != 0) ? __expf(c[nt][3]) : 0.f;
            rsA += p[nt][0] + p[nt][1];
            rsB += p[nt][2] + p[nt][3];
            int cg = kb + wn * 32 + nt * 8 + 2 * tg;
            *(float2*)(attn + arowA + cg) = make_float2(p[nt][0], p[nt][1]);
            *(float2*)(attn + arowB + cg) = make_float2(p[nt][2], p[nt][3]);
        }

        unsigned pa[2][4];
        #pragma unroll
        for (int k2 = 0; k2 < 2; k2++) {
            pa[k2][0] = __float_as_uint(__uint_as_float(0)); // placeholder, set below
            __half2 h0 = __floats2half2_rn(p[2 * k2][0], p[2 * k2][1]);
            __half2 h1 = __floats2half2_rn(p[2 * k2][2], p[2 * k2][3]);
            __half2 h2 = __floats2half2_rn(p[2 * k2 + 1][0], p[2 * k2 + 1][1]);
            __half2 h3 = __floats2half2_rn(p[2 * k2 + 1][2], p[2 * k2 + 1][3]);
            pa[k2][0] = *(unsigned*)&h0;
            pa[k2][1] = *(unsigned*)&h1;
            pa[k2][2] = *(unsigned*)&h2;
            pa[k2][3] = *(unsigned*)&h3;
        }

        // PV: warp's 32-k slice, all 64 d cols (8 ntiles), accumulate in regs
        #pragma unroll
        for (int nt2 = 0; nt2 < 8; nt2++) {
            #pragma unroll
            for (int k2 = 0; k2 < 2; k2++) {
                const __half* vp = Vs + (nt2 * 8 + g) * 136 + wn * 32 + k2 * 16 + 2 * tg;
                unsigned b[2];
                b[0] = *(const uint32_t*)vp;
                b[1] = *(const uint32_t*)(vp + 8);
                mmah(pvacc[nt2], pa[k2], b);
            }
        }
    }

    // rowsum: reduce over tg within quad, then across wn warps via smem atomics
    rsA += __shfl_xor_sync(0xffffffffu, rsA, 1);
    rsA += __shfl_xor_sync(0xffffffffu, rsA, 2);
    rsB += __shfl_xor_sync(0xffffffffu, rsB, 1);
    rsB += __shfl_xor_sync(0xffffffffu, rsB, 2);
    if (tg == 0) {
        atomicAdd(&rows[wm * 16 + g    ], rsA);
        atomicAdd(&rows[wm * 16 + g + 8], rsB);
    }
    __syncthreads();   // all chunk reads + atomics done
    if (tid < 64) rows[tid] = 1.0f / rows[tid];

    // PV cross-warp (wn) reduction via smem scratch (reuses K/Vt region)
    float* scr = (float*)(smg + SMB_K(0));
    #pragma unroll
    for (int nt2 = 0; nt2 < 8; nt2++) {
        int col = nt2 * 8 + 2 * tg;
        *(float2*)&scr[wn * 4096 + (wm * 16 + g    ) * 64 + col] =
            make_float2(pvacc[nt2][0], pvacc[nt2][1]);
        *(float2*)&scr[wn * 4096 + (wm * 16 + g + 8) * 64 + col] =
            make_float2(pvacc[nt2][2], pvacc[nt2][3]);
    }
    __syncthreads();

    // final X write: 8 cols per thread
    {
        int r = tid >> 3, cg = (tid & 7) * 8;
        float4 s0v = make_float4(0, 0, 0, 0), s1v = make_float4(0, 0, 0, 0);
        #pragma unroll
        for (int ww = 0; ww < 4; ww++) {
            float4 u0 = *(float4*)&scr[ww * 4096 + r * 64 + cg];
            float4 u1 = *(float4*)&scr[ww * 4096 + r * 64 + cg + 4];
            s0v.x += u0.x; s0v.y += u0.y; s0v.z += u0.z; s0v.w += u0.w;
            s1v.x += u1.x; s1v.y += u1.y; s1v.z += u1.z; s1v.w += u1.w;
        }
        float inv = rows[r];
        s0v.x *= inv; s0v.y *= inv; s0v.z *= inv; s0v.w *= inv;
        s1v.x *= inv; s1v.y *= inv; s1v.z *= inv; s1v.w *= inv;
        float* xp = Xo + (size_t)(bB * S_ + s0 + r) * HID_ + h * 64 + cg;
        *(float4*)xp = s0v;
        *(float4*)(xp + 4) = s1v;
    }

    // rescale this block's 64x2048 attn slab
    {
        float4* slab = (float4*)(attn + ((size_t)z * S_ + s0) * S_);
        #pragma unroll 4
        for (int j = 0; j < 64; j++) {
            int lin = j * 512 + tid;
            int r = lin >> 9, c = lin & 511;
            float inv = rows[r];
            float4 t = slab[(size_t)r * 512 + c];
            t.x *= inv; t.y *= inv; t.z *= inv; t.w *= inv;
            slab[(size_t)r * 512 + c] = t;
        }
    }
}

// ---------------------------------------------------------------------------
// Launch
// ---------------------------------------------------------------------------
extern "C" void kernel_launch(void* const* d_in, const int* in_sizes, int n_in,
                              void* d_out, int out_size)
{
    const float* q    = (const float*)d_in[0];
    const float* k    = (const float*)d_in[1];
    const float* v    = (const float*)d_in[2];
    const int*   mask = (const int*)  d_in[3];
    const float* Wq   = (const float*)d_in[4];
    const float* bq   = (const float*)d_in[5];
    const float* Wk   = (const float*)d_in[6];
    const float* bk   = (const float*)d_in[7];
    const float* Wv   = (const float*)d_in[8];
    const float* bv   = (const float*)d_in[9];
    const float* Wo   = (const float*)d_in[10];
    const float* bo   = (const float*)d_in[11];

    float* out = (float*)d_out;

    __half *Qhp, *Khp, *Vhp, *Vtp;
    float *Xf, *scr;
    cudaGetSymbolAddress((void**)&Qhp, g_Qh);
    cudaGetSymbolAddress((void**)&Khp, g_Kh);
    cudaGetSymbolAddress((void**)&Vhp, g_Vh);
    cudaGetSymbolAddress((void**)&Vtp, g_Vt);
    cudaGetSymbolAddress((void**)&Xf,  g_X);
    cudaGetSymbolAddress((void**)&scr, g_attn_scratch);

    const size_t out_elems  = (size_t)M_ * HID_;
    const size_t attn_elems = (size_t)BH_ * S_ * S_;
    float* attn = ((size_t)out_size >= out_elems + attn_elems) ? out + out_elems : scr;

    cudaFuncSetAttribute(attn_fa, cudaFuncAttributeMaxDynamicSharedMemorySize, ATTN_SMEM);

    // Q/K/V projections -> half (Q pre-scaled by softmax scale 1/8)
    ProjArgs pq{q, Wq, bq, nullptr, Qhp, 0.125f};
    ProjArgs pk{k, Wk, bk, nullptr, Khp, 1.0f};
    ProjArgs pv{v, Wv, bv, nullptr, Vhp, 1.0f};
    proj_tf32<<<dim3(8, 32, 3), 256>>>(pq, pk, pv);

    vtrans<<<dim3(32, 16), 256>>>(Vhp, Vtp);

    attn_fa<<<dim3(32, 16), 512, ATTN_SMEM>>>(Qhp, Khp, Vtp, mask, attn, Xf);

    ProjArgs po{Xf, Wo, bo, out, nullptr, 1.0f};
    proj_tf32<<<dim3(8, 32, 1), 256>>>(po, po, po);
}

// round 7
// speedup vs baseline: 3.4833x; 1.2339x over previous
#include <cuda_runtime.h>
#include <cuda_fp16.h>
#include <math.h>
#include <stdint.h>

#define B_    2
#define S_    2048
#define HID_  512
#define H_    8
#define BH_   16
#define M_    4096

// Scratch (device globals; no allocation allowed)
__device__ __align__(256) __half g_Qh[M_ * HID_];
__device__ __align__(256) __half g_Kh[M_ * HID_];
__device__ __align__(256) __half g_Vh[M_ * HID_];
__device__ __align__(256) __half g_Vt[BH_ * 64 * S_];   // [z][d][s]
__device__ float g_X [M_ * HID_];
__device__ float g_attn_scratch[(size_t)BH_ * S_ * S_];

// ---------------------------------------------------------------------------
// helpers
// ---------------------------------------------------------------------------
__device__ __forceinline__ unsigned f2tf(float x) {
    unsigned u;
    asm("cvt.rna.tf32.f32 %0, %1;" : "=r"(u) : "f"(x));
    return u;
}

__device__ __forceinline__ void mma8(float c[4], const unsigned a[4], const unsigned b[2]) {
    asm volatile(
        "mma.sync.aligned.m16n8k8.row.col.f32.tf32.tf32.f32 "
        "{%0,%1,%2,%3},{%4,%5,%6,%7},{%8,%9},{%0,%1,%2,%3};"
        : "+f"(c[0]), "+f"(c[1]), "+f"(c[2]), "+f"(c[3])
        : "r"(a[0]), "r"(a[1]), "r"(a[2]), "r"(a[3]),
          "r"(b[0]), "r"(b[1]));
}

__device__ __forceinline__ void mmah(float c[4], const unsigned a[4], const unsigned b[2]) {
    asm volatile(
        "mma.sync.aligned.m16n8k16.row.col.f32.f16.f16.f32 "
        "{%0,%1,%2,%3},{%4,%5,%6,%7},{%8,%9},{%0,%1,%2,%3};"
        : "+f"(c[0]), "+f"(c[1]), "+f"(c[2]), "+f"(c[3])
        : "r"(a[0]), "r"(a[1]), "r"(a[2]), "r"(a[3]),
          "r"(b[0]), "r"(b[1]));
}

__device__ __forceinline__ void cp16(uint32_t saddr, const void* g) {
    asm volatile("cp.async.cg.shared.global [%0], [%1], 16;" :: "r"(saddr), "l"(g));
}
__device__ __forceinline__ uint32_t sptr(const void* p) {
    return (uint32_t)__cvta_generic_to_shared(p);
}

// ---------------------------------------------------------------------------
// Projection GEMM v2: cp.async double-buffered, tf32 cvt at fragment build.
// Y = X @ W^T + b. 128m x 64n tile, k=32 stages, 2 CTAs/SM.
// ---------------------------------------------------------------------------
struct ProjArgs { const float *X, *W, *b; float *Yf; __half *Yh; float scale; };

#define PJ_A(s) ((s) * 6912)
#define PJ_B(s) ((s) * 6912 + 4608)
#define PJ_SMEM (2 * 6912 * 4)

__global__ void __launch_bounds__(256, 2)
proj_tf32(ProjArgs a0, ProjArgs a1, ProjArgs a2)
{
    const ProjArgs& A_ = (blockIdx.z == 0) ? a0 : (blockIdx.z == 1) ? a1 : a2;
    const float* __restrict__ Xg = A_.X;
    const float* __restrict__ Wg = A_.W;
    const float* __restrict__ bias = A_.b;

    extern __shared__ float psm[];
    const uint32_t sb = sptr(psm);

    const int tid = threadIdx.x;
    const int lane = tid & 31, wid = tid >> 5;
    const int g = lane >> 2, tg = lane & 3;
    const int wm = wid & 3, wn = wid >> 2;
    const int m0 = blockIdx.y * 128, n0 = blockIdx.x * 64;

    auto stage = [&](int k0, int s) {
        #pragma unroll
        for (int j = 0; j < 4; j++) {
            int lin = tid + j * 256;
            int r = lin >> 3, c4 = lin & 7;
            cp16(sb + (PJ_A(s) + r * 36 + c4 * 4) * 4,
                 Xg + (size_t)(m0 + r) * 512 + k0 + c4 * 4);
        }
        #pragma unroll
        for (int j = 0; j < 2; j++) {
            int lin = tid + j * 256;
            int r = lin >> 3, c4 = lin & 7;
            cp16(sb + (PJ_B(s) + r * 36 + c4 * 4) * 4,
                 Wg + (size_t)(n0 + r) * 512 + k0 + c4 * 4);
        }
        asm volatile("cp.async.commit_group;");
    };

    float acc[2][4][4] = {};

    stage(0, 0);
    for (int t = 0; t < 16; t++) {
        if (t < 15) stage((t + 1) * 32, (t + 1) & 1);
        if (t < 15) asm volatile("cp.async.wait_group 1;");
        else        asm volatile("cp.async.wait_group 0;");
        __syncthreads();

        const float* As = psm + PJ_A(t & 1);
        const float* Bs = psm + PJ_B(t & 1);

        #pragma unroll
        for (int ks = 0; ks < 4; ks++) {
            unsigned af[2][4], bf[4][2];
            #pragma unroll
            for (int mi = 0; mi < 2; mi++) {
                int rb = wm * 32 + mi * 16;
                af[mi][0] = f2tf(As[(rb + g    ) * 36 + ks * 8 + tg    ]);
                af[mi][1] = f2tf(As[(rb + g + 8) * 36 + ks * 8 + tg    ]);
                af[mi][2] = f2tf(As[(rb + g    ) * 36 + ks * 8 + tg + 4]);
                af[mi][3] = f2tf(As[(rb + g + 8) * 36 + ks * 8 + tg + 4]);
            }
            #pragma unroll
            for (int ni = 0; ni < 4; ni++) {
                int rb = wn * 32 + ni * 8;
                bf[ni][0] = f2tf(Bs[(rb + g) * 36 + ks * 8 + tg    ]);
                bf[ni][1] = f2tf(Bs[(rb + g) * 36 + ks * 8 + tg + 4]);
            }
            #pragma unroll
            for (int mi = 0; mi < 2; mi++)
                #pragma unroll
                for (int ni = 0; ni < 4; ni++)
                    mma8(acc[mi][ni], af[mi], bf[ni]);
        }
        __syncthreads();
    }

    const float scale = A_.scale;
    #pragma unroll
    for (int mi = 0; mi < 2; mi++) {
        int r0 = m0 + wm * 32 + mi * 16 + g;
        #pragma unroll
        for (int ni = 0; ni < 4; ni++) {
            int c0 = n0 + wn * 32 + ni * 8 + 2 * tg;
            float b0v = __ldg(bias + c0), b1v = __ldg(bias + c0 + 1);
            float y00 = acc[mi][ni][0] + b0v, y01 = acc[mi][ni][1] + b1v;
            float y10 = acc[mi][ni][2] + b0v, y11 = acc[mi][ni][3] + b1v;
            if (A_.Yh) {
                A_.Yh[(size_t)r0 * 512 + c0    ] = __float2half_rn(y00 * scale);
                A_.Yh[(size_t)r0 * 512 + c0 + 1] = __float2half_rn(y01 * scale);
                A_.Yh[(size_t)(r0 + 8) * 512 + c0    ] = __float2half_rn(y10 * scale);
                A_.Yh[(size_t)(r0 + 8) * 512 + c0 + 1] = __float2half_rn(y11 * scale);
            } else {
                A_.Yf[(size_t)r0 * 512 + c0    ] = y00;
                A_.Yf[(size_t)r0 * 512 + c0 + 1] = y01;
                A_.Yf[(size_t)(r0 + 8) * 512 + c0    ] = y10;
                A_.Yf[(size_t)(r0 + 8) * 512 + c0 + 1] = y11;
            }
        }
    }
}

// ---------------------------------------------------------------------------
// V transpose: Vh [b, s, hid] (half) -> Vt [z][d][s] (half)
// ---------------------------------------------------------------------------
__global__ void __launch_bounds__(256)
vtrans(const __half* __restrict__ Vh, __half* __restrict__ Vt)
{
    __shared__ __half ts[64 * 72];
    const int tid = threadIdx.x;
    const int z = blockIdx.y, bB = z >> 3, h = z & 7;
    const int s0 = blockIdx.x * 64;

    #pragma unroll
    for (int j = 0; j < 8; j++) {
        int lin = tid + j * 256;
        int s = lin >> 5, du = lin & 31;
        *(uint32_t*)(ts + s * 72 + du * 2) =
            *(const uint32_t*)(Vh + (size_t)(bB * S_ + s0 + s) * HID_ + h * 64 + du * 2);
    }
    __syncthreads();
    #pragma unroll
    for (int j = 0; j < 8; j++) {
        int lin = tid + j * 256;
        int d = lin >> 5, su = lin & 31;
        __half2 o = __halves2half2(ts[(2 * su) * 72 + d], ts[(2 * su + 1) * 72 + d]);
        *(__half2*)(Vt + ((size_t)z * 64 + d) * S_ + s0 + su * 2) = o;
    }
}

// ---------------------------------------------------------------------------
// Two-pass FA attention (fp16 mma).
// Pass A: scores+exp -> rowsum + PV (register-resident P, no attn write).
// Pass B: recompute scores, exp, multiply by inv rowsum, single normalized
//         attn write. K re-streamed (L2-resident).
// ---------------------------------------------------------------------------
#define SMB_Q    0u
#define SMB_K(s) (9216u + (s) * 18432u)
#define SMB_V(s) (64512u + (s) * 17408u)
#define SMB_RS   116736u
#define ATTN_SMEM (117008 + 16)

__global__ void __launch_bounds__(512, 1)
attn_fa(const __half* __restrict__ Qh, const __half* __restrict__ Kh,
        const __half* __restrict__ Vtg, const int* __restrict__ mask,
        float* __restrict__ attn, float* __restrict__ Xo)
{
    extern __shared__ char smg[];
    const uint32_t sb = sptr(smg);

    const int tid = threadIdx.x, lane = tid & 31, w = tid >> 5;
    const int g = lane >> 2, tg = lane & 3;
    const int wm = w & 3, wn = w >> 2;
    const int z = blockIdx.y, strip = blockIdx.x;
    const int bB = z >> 3, h = z & 7;
    const int s0 = strip * 64;

    float* rows = (float*)(smg + SMB_RS);
    if (tid < 64) rows[tid] = 0.f;

    const __half* Qsrc = Qh + (size_t)(bB * S_ + s0) * HID_ + h * 64;
    const __half* Ksrc = Kh + (size_t)(bB * S_) * HID_ + h * 64;
    const __half* Vsrc = Vtg + (size_t)z * 64 * S_;

    auto loadKV = [&](int chunk, int st) {
        const int kb = chunk * 128;
        #pragma unroll
        for (int j = 0; j < 2; j++) {
            int idx = tid + j * 512;
            int r = idx >> 3, c16 = idx & 7;
            cp16(sb + SMB_K(st) + (uint32_t)r * 144u + (uint32_t)c16 * 16u,
                 Ksrc + (size_t)(kb + r) * HID_ + c16 * 8);
        }
        #pragma unroll
        for (int j = 0; j < 2; j++) {
            int idx = tid + j * 512;
            int d = idx >> 4, c16 = idx & 15;
            cp16(sb + SMB_V(st) + (uint32_t)d * 272u + (uint32_t)c16 * 16u,
                 Vsrc + (size_t)d * S_ + kb + c16 * 8);
        }
        asm volatile("cp.async.commit_group;");
    };
    auto loadKo = [&](int chunk, int st) {
        const int kb = chunk * 128;
        #pragma unroll
        for (int j = 0; j < 2; j++) {
            int idx = tid + j * 512;
            int r = idx >> 3, c16 = idx & 7;
            cp16(sb + SMB_K(st) + (uint32_t)r * 144u + (uint32_t)c16 * 16u,
                 Ksrc + (size_t)(kb + r) * HID_ + c16 * 8);
        }
        asm volatile("cp.async.commit_group;");
    };

    // prologue: Q + chunk0 (group0), chunk1 (group1)
    {
        int r = tid >> 3, c16 = tid & 7;
        cp16(sb + SMB_Q + (uint32_t)r * 144u + (uint32_t)c16 * 16u,
             Qsrc + (size_t)r * HID_ + c16 * 8);
    }
    loadKV(0, 0);
    loadKV(1, 1);
    asm volatile("cp.async.wait_group 1;");
    __syncthreads();

    const __half* Qs = (const __half*)(smg + SMB_Q);
    unsigned qa[4][4];
    #pragma unroll
    for (int ks = 0; ks < 4; ks++) {
        const __half* qr0 = Qs + (wm * 16 + g) * 72 + ks * 16 + 2 * tg;
        const __half* qr1 = qr0 + 8 * 72;
        qa[ks][0] = *(const uint32_t*)qr0;
        qa[ks][1] = *(const uint32_t*)qr1;
        qa[ks][2] = *(const uint32_t*)(qr0 + 8);
        qa[ks][3] = *(const uint32_t*)(qr1 + 8);
    }

    float pvacc[8][4] = {};
    float rsA = 0.f, rsB = 0.f;

    const int rA = bB * S_ + s0 + wm * 16 + g;
    const size_t arowA = ((size_t)z * S_ + s0 + wm * 16 + g) * S_;
    const size_t arowB = arowA + 8 * S_;

    // ------------------------- PASS A -------------------------
    for (int it = 0; it < 16; it++) {
        const int kb = it * 128;
        const int st = it % 3;

        int2 mA[4], mB[4];
        #pragma unroll
        for (int nt = 0; nt < 4; nt++) {
            int cg = kb + wn * 32 + nt * 8 + 2 * tg;
            mA[nt] = __ldg((const int2*)(mask + (size_t)rA * S_ + cg));
            mB[nt] = __ldg((const int2*)(mask + (size_t)(rA + 8) * S_ + cg));
        }

        if (it > 0) {
            if (it < 15) asm volatile("cp.async.wait_group 1;");
            else         asm volatile("cp.async.wait_group 0;");
            __syncthreads();
        }
        if (it + 2 < 16) loadKV(it + 2, (it + 2) % 3);

        const __half* Ks = (const __half*)(smg + SMB_K(st));
        const __half* Vs = (const __half*)(smg + SMB_V(st));

        float c[4][4] = {};
        #pragma unroll
        for (int ks = 0; ks < 4; ks++) {
            #pragma unroll
            for (int nt = 0; nt < 4; nt++) {
                const __half* kp = Ks + (wn * 32 + nt * 8 + g) * 72 + ks * 16 + 2 * tg;
                unsigned b[2];
                b[0] = *(const uint32_t*)kp;
                b[1] = *(const uint32_t*)(kp + 8);
                mmah(c[nt], qa[ks], b);
            }
        }

        float p[4][4];
        #pragma unroll
        for (int nt = 0; nt < 4; nt++) {
            p[nt][0] = (mA[nt].x != 0) ? __expf(c[nt][0]) : 0.f;
            p[nt][1] = (mA[nt].y != 0) ? __expf(c[nt][1]) : 0.f;
            p[nt][2] = (mB[nt].x != 0) ? __expf(c[nt][2]) : 0.f;
            p[nt][3] = (mB[nt].y != 0) ? __expf(c[nt][3]) : 0.f;
            rsA += p[nt][0] + p[nt][1];
            rsB += p[nt][2] + p[nt][3];
        }

        unsigned pa[2][4];
        #pragma unroll
        for (int k2 = 0; k2 < 2; k2++) {
            __half2 h0 = __floats2half2_rn(p[2 * k2][0], p[2 * k2][1]);
            __half2 h1 = __floats2half2_rn(p[2 * k2][2], p[2 * k2][3]);
            __half2 h2 = __floats2half2_rn(p[2 * k2 + 1][0], p[2 * k2 + 1][1]);
            __half2 h3 = __floats2half2_rn(p[2 * k2 + 1][2], p[2 * k2 + 1][3]);
            pa[k2][0] = *(unsigned*)&h0;
            pa[k2][1] = *(unsigned*)&h1;
            pa[k2][2] = *(unsigned*)&h2;
            pa[k2][3] = *(unsigned*)&h3;
        }

        #pragma unroll
        for (int nt2 = 0; nt2 < 8; nt2++) {
            #pragma unroll
            for (int k2 = 0; k2 < 2; k2++) {
                const __half* vp = Vs + (nt2 * 8 + g) * 136 + wn * 32 + k2 * 16 + 2 * tg;
                unsigned b[2];
                b[0] = *(const uint32_t*)vp;
                b[1] = *(const uint32_t*)(vp + 8);
                mmah(pvacc[nt2], pa[k2], b);
            }
        }
    }

    // rowsum reduction
    rsA += __shfl_xor_sync(0xffffffffu, rsA, 1);
    rsA += __shfl_xor_sync(0xffffffffu, rsA, 2);
    rsB += __shfl_xor_sync(0xffffffffu, rsB, 1);
    rsB += __shfl_xor_sync(0xffffffffu, rsB, 2);
    if (tg == 0) {
        atomicAdd(&rows[wm * 16 + g    ], rsA);
        atomicAdd(&rows[wm * 16 + g + 8], rsB);
    }
    __syncthreads();   // chunk15 smem reads + rowsum atomics complete

    // pass B prologue (overlaps PV reduction): K chunks 0,1 into stages 0,1
    loadKo(0, 0);
    loadKo(1, 1);

    if (tid < 64) rows[tid] = 1.0f / rows[tid];

    // PV cross-warp reduction: 4 disjoint 16KB areas (V0,V1,V2,K2), no atomics
    const uint32_t scrOff[4] = { SMB_V(0), SMB_V(1), SMB_V(2), SMB_K(2) };
    {
        float* sw = (float*)(smg + scrOff[wn]);
        #pragma unroll
        for (int nt2 = 0; nt2 < 8; nt2++) {
            int col = nt2 * 8 + 2 * tg;
            *(float2*)&sw[(wm * 16 + g    ) * 64 + col] =
                make_float2(pvacc[nt2][0], pvacc[nt2][1]);
            *(float2*)&sw[(wm * 16 + g + 8) * 64 + col] =
                make_float2(pvacc[nt2][2], pvacc[nt2][3]);
        }
    }
    __syncthreads();

    // X write: 8 cols per thread, normalized
    {
        int r = tid >> 3, cg = (tid & 7) * 8;
        float4 s0v = make_float4(0, 0, 0, 0), s1v = make_float4(0, 0, 0, 0);
        #pragma unroll
        for (int ww = 0; ww < 4; ww++) {
            const float* sw = (const float*)(smg + scrOff[ww]);
            float4 u0 = *(const float4*)&sw[r * 64 + cg];
            float4 u1 = *(const float4*)&sw[r * 64 + cg + 4];
            s0v.x += u0.x; s0v.y += u0.y; s0v.z += u0.z; s0v.w += u0.w;
            s1v.x += u1.x; s1v.y += u1.y; s1v.z += u1.z; s1v.w += u1.w;
        }
        float inv = rows[r];
        s0v.x *= inv; s0v.y *= inv; s0v.z *= inv; s0v.w *= inv;
        s1v.x *= inv; s1v.y *= inv; s1v.z *= inv; s1v.w *= inv;
        float* xp = Xo + (size_t)(bB * S_ + s0 + r) * HID_ + h * 64 + cg;
        *(float4*)xp = s0v;
        *(float4*)(xp + 4) = s1v;
    }

    // ------------------------- PASS B -------------------------
    asm volatile("cp.async.wait_group 1;");
    __syncthreads();   // chunk0 ready; X-write smem reads done before K(2) reuse

    const float invA = rows[wm * 16 + g];
    const float invB = rows[wm * 16 + g + 8];

    for (int it = 0; it < 16; it++) {
        const int kb = it * 128;
        const int st = it % 3;

        int2 mA[4], mB[4];
        #pragma unroll
        for (int nt = 0; nt < 4; nt++) {
            int cg = kb + wn * 32 + nt * 8 + 2 * tg;
            mA[nt] = __ldg((const int2*)(mask + (size_t)rA * S_ + cg));
            mB[nt] = __ldg((const int2*)(mask + (size_t)(rA + 8) * S_ + cg));
        }

        if (it > 0) {
            if (it < 15) asm volatile("cp.async.wait_group 1;");
            else         asm volatile("cp.async.wait_group 0;");
            __syncthreads();
        }
        if (it + 2 < 16) loadKo(it + 2, (it + 2) % 3);

        const __half* Ks = (const __half*)(smg + SMB_K(st));

        float c[4][4] = {};
        #pragma unroll
        for (int ks = 0; ks < 4; ks++) {
            #pragma unroll
            for (int nt = 0; nt < 4; nt++) {
                const __half* kp = Ks + (wn * 32 + nt * 8 + g) * 72 + ks * 16 + 2 * tg;
                unsigned b[2];
                b[0] = *(const uint32_t*)kp;
                b[1] = *(const uint32_t*)(kp + 8);
                mmah(c[nt], qa[ks], b);
            }
        }

        #pragma unroll
        for (int nt = 0; nt < 4; nt++) {
            int cg = kb + wn * 32 + nt * 8 + 2 * tg;
            float p0 = (mA[nt].x != 0) ? __expf(c[nt][0]) * invA : 0.f;
            float p1 = (mA[nt].y != 0) ? __expf(c[nt][1]) * invA : 0.f;
            float p2 = (mB[nt].x != 0) ? __expf(c[nt][2]) * invB : 0.f;
            float p3 = (mB[nt].y != 0) ? __expf(c[nt][3]) * invB : 0.f;
            *(float2*)(attn + arowA + cg) = make_float2(p0, p1);
            *(float2*)(attn + arowB + cg) = make_float2(p2, p3);
        }
    }
}

// ---------------------------------------------------------------------------
// Launch
// ---------------------------------------------------------------------------
extern "C" void kernel_launch(void* const* d_in, const int* in_sizes, int n_in,
                              void* d_out, int out_size)
{
    const float* q    = (const float*)d_in[0];
    const float* k    = (const float*)d_in[1];
    const float* v    = (const float*)d_in[2];
    const int*   mask = (const int*)  d_in[3];
    const float* Wq   = (const float*)d_in[4];
    const float* bq   = (const float*)d_in[5];
    const float* Wk   = (const float*)d_in[6];
    const float* bk   = (const float*)d_in[7];
    const float* Wv   = (const float*)d_in[8];
    const float* bv   = (const float*)d_in[9];
    const float* Wo   = (const float*)d_in[10];
    const float* bo   = (const float*)d_in[11];

    float* out = (float*)d_out;

    __half *Qhp, *Khp, *Vhp, *Vtp;
    float *Xf, *scr;
    cudaGetSymbolAddress((void**)&Qhp, g_Qh);
    cudaGetSymbolAddress((void**)&Khp, g_Kh);
    cudaGetSymbolAddress((void**)&Vhp, g_Vh);
    cudaGetSymbolAddress((void**)&Vtp, g_Vt);
    cudaGetSymbolAddress((void**)&Xf,  g_X);
    cudaGetSymbolAddress((void**)&scr, g_attn_scratch);

    const size_t out_elems  = (size_t)M_ * HID_;
    const size_t attn_elems = (size_t)BH_ * S_ * S_;
    float* attn = ((size_t)out_size >= out_elems + attn_elems) ? out + out_elems : scr;

    cudaFuncSetAttribute(attn_fa, cudaFuncAttributeMaxDynamicSharedMemorySize, ATTN_SMEM);
    cudaFuncSetAttribute(proj_tf32, cudaFuncAttributeMaxDynamicSharedMemorySize, PJ_SMEM);

    ProjArgs pq{q, Wq, bq, nullptr, Qhp, 0.125f};
    ProjArgs pk{k, Wk, bk, nullptr, Khp, 1.0f};
    ProjArgs pv{v, Wv, bv, nullptr, Vhp, 1.0f};
    proj_tf32<<<dim3(8, 32, 3), 256, PJ_SMEM>>>(pq, pk, pv);

    vtrans<<<dim3(32, 16), 256>>>(Vhp, Vtp);

    attn_fa<<<dim3(32, 16), 512, ATTN_SMEM>>>(Qhp, Khp, Vtp, mask, attn, Xf);

    ProjArgs po{Xf, Wo, bo, out, nullptr, 1.0f};
    proj_tf32<<<dim3(8, 32, 1), 256, PJ_SMEM>>>(po, po, po);
}

// round 8
// speedup vs baseline: 3.8636x; 1.1092x over previous
#include <cuda_runtime.h>
#include <cuda_fp16.h>
#include <math.h>
#include <stdint.h>

#define B_    2
#define S_    2048
#define HID_  512
#define H_    8
#define BH_   16
#define M_    4096

// Scratch (device globals; no allocation allowed)
__device__ __align__(256) __half g_Qh[M_ * HID_];
__device__ __align__(256) __half g_Kh[M_ * HID_];
__device__ __align__(256) __half g_Vh[M_ * HID_];
__device__ __align__(256) __half g_Vt[BH_ * 64 * S_];   // [z][d][s]
__device__ float g_X [M_ * HID_];
__device__ float g_rowinv[BH_ * S_];
__device__ uint32_t g_pm[M_ * 64];                      // packed mask bits, 1MB
__device__ float g_attn_scratch[(size_t)BH_ * S_ * S_];

// ---------------------------------------------------------------------------
// helpers
// ---------------------------------------------------------------------------
__device__ __forceinline__ unsigned f2tf(float x) {
    unsigned u;
    asm("cvt.rna.tf32.f32 %0, %1;" : "=r"(u) : "f"(x));
    return u;
}

__device__ __forceinline__ void mma8(float c[4], const unsigned a[4], const unsigned b[2]) {
    asm volatile(
        "mma.sync.aligned.m16n8k8.row.col.f32.tf32.tf32.f32 "
        "{%0,%1,%2,%3},{%4,%5,%6,%7},{%8,%9},{%0,%1,%2,%3};"
        : "+f"(c[0]), "+f"(c[1]), "+f"(c[2]), "+f"(c[3])
        : "r"(a[0]), "r"(a[1]), "r"(a[2]), "r"(a[3]),
          "r"(b[0]), "r"(b[1]));
}

__device__ __forceinline__ void mmah(float c[4], const unsigned a[4], const unsigned b[2]) {
    asm volatile(
        "mma.sync.aligned.m16n8k16.row.col.f32.f16.f16.f32 "
        "{%0,%1,%2,%3},{%4,%5,%6,%7},{%8,%9},{%0,%1,%2,%3};"
        : "+f"(c[0]), "+f"(c[1]), "+f"(c[2]), "+f"(c[3])
        : "r"(a[0]), "r"(a[1]), "r"(a[2]), "r"(a[3]),
          "r"(b[0]), "r"(b[1]));
}

__device__ __forceinline__ void cp16(uint32_t saddr, const void* g) {
    asm volatile("cp.async.cg.shared.global [%0], [%1], 16;" :: "r"(saddr), "l"(g));
}
__device__ __forceinline__ uint32_t sptr(const void* p) {
    return (uint32_t)__cvta_generic_to_shared(p);
}

// ---------------------------------------------------------------------------
// Projection GEMM: 3-stage cp.async, tf32 cvt at fragment build, 2 CTAs/SM.
// ---------------------------------------------------------------------------
struct ProjArgs { const float *X, *W, *b; float *Yf; __half *Yh; float scale; };

#define PJ_A(s) ((s) * 6912)
#define PJ_B(s) ((s) * 6912 + 4608)
#define PJ_SMEM (3 * 6912 * 4)

__global__ void __launch_bounds__(256, 2)
proj_tf32(ProjArgs a0, ProjArgs a1, ProjArgs a2)
{
    const ProjArgs& A_ = (blockIdx.z == 0) ? a0 : (blockIdx.z == 1) ? a1 : a2;
    const float* __restrict__ Xg = A_.X;
    const float* __restrict__ Wg = A_.W;
    const float* __restrict__ bias = A_.b;

    extern __shared__ float psm[];
    const uint32_t sb = sptr(psm);

    const int tid = threadIdx.x;
    const int lane = tid & 31, wid = tid >> 5;
    const int g = lane >> 2, tg = lane & 3;
    const int wm = wid & 3, wn = wid >> 2;
    const int m0 = blockIdx.y * 128, n0 = blockIdx.x * 64;

    auto stage = [&](int k0, int s) {
        #pragma unroll
        for (int j = 0; j < 4; j++) {
            int lin = tid + j * 256;
            int r = lin >> 3, c4 = lin & 7;
            cp16(sb + (PJ_A(s) + r * 36 + c4 * 4) * 4,
                 Xg + (size_t)(m0 + r) * 512 + k0 + c4 * 4);
        }
        #pragma unroll
        for (int j = 0; j < 2; j++) {
            int lin = tid + j * 256;
            int r = lin >> 3, c4 = lin & 7;
            cp16(sb + (PJ_B(s) + r * 36 + c4 * 4) * 4,
                 Wg + (size_t)(n0 + r) * 512 + k0 + c4 * 4);
        }
        asm volatile("cp.async.commit_group;");
    };

    float acc[2][4][4] = {};

    stage(0, 0);
    stage(32, 1);
    for (int t = 0; t < 16; t++) {
        if (t < 15) asm volatile("cp.async.wait_group 1;");
        else        asm volatile("cp.async.wait_group 0;");
        __syncthreads();
        if (t + 2 < 16) stage((t + 2) * 32, (t + 2) % 3);

        const float* As = psm + PJ_A(t % 3);
        const float* Bs = psm + PJ_B(t % 3);

        #pragma unroll
        for (int ks = 0; ks < 4; ks++) {
            unsigned af[2][4], bf[4][2];
            #pragma unroll
            for (int mi = 0; mi < 2; mi++) {
                int rb = wm * 32 + mi * 16;
                af[mi][0] = f2tf(As[(rb + g    ) * 36 + ks * 8 + tg    ]);
                af[mi][1] = f2tf(As[(rb + g + 8) * 36 + ks * 8 + tg    ]);
                af[mi][2] = f2tf(As[(rb + g    ) * 36 + ks * 8 + tg + 4]);
                af[mi][3] = f2tf(As[(rb + g + 8) * 36 + ks * 8 + tg + 4]);
            }
            #pragma unroll
            for (int ni = 0; ni < 4; ni++) {
                int rb = wn * 32 + ni * 8;
                bf[ni][0] = f2tf(Bs[(rb + g) * 36 + ks * 8 + tg    ]);
                bf[ni][1] = f2tf(Bs[(rb + g) * 36 + ks * 8 + tg + 4]);
            }
            #pragma unroll
            for (int mi = 0; mi < 2; mi++)
                #pragma unroll
                for (int ni = 0; ni < 4; ni++)
                    mma8(acc[mi][ni], af[mi], bf[ni]);
        }
    }

    const float scale = A_.scale;
    #pragma unroll
    for (int mi = 0; mi < 2; mi++) {
        int r0 = m0 + wm * 32 + mi * 16 + g;
        #pragma unroll
        for (int ni = 0; ni < 4; ni++) {
            int c0 = n0 + wn * 32 + ni * 8 + 2 * tg;
            float b0v = __ldg(bias + c0), b1v = __ldg(bias + c0 + 1);
            float y00 = acc[mi][ni][0] + b0v, y01 = acc[mi][ni][1] + b1v;
            float y10 = acc[mi][ni][2] + b0v, y11 = acc[mi][ni][3] + b1v;
            if (A_.Yh) {
                __half2 h0 = __floats2half2_rn(y00 * scale, y01 * scale);
                __half2 h1 = __floats2half2_rn(y10 * scale, y11 * scale);
                *(__half2*)(A_.Yh + (size_t)r0 * 512 + c0) = h0;
                *(__half2*)(A_.Yh + (size_t)(r0 + 8) * 512 + c0) = h1;
            } else {
                *(float2*)(A_.Yf + (size_t)r0 * 512 + c0) = make_float2(y00, y01);
                *(float2*)(A_.Yf + (size_t)(r0 + 8) * 512 + c0) = make_float2(y10, y11);
            }
        }
    }
}

// ---------------------------------------------------------------------------
// V transpose: Vh [b, s, hid] (half) -> Vt [z][d][s] (half)
// ---------------------------------------------------------------------------
__global__ void __launch_bounds__(256)
vtrans(const __half* __restrict__ Vh, __half* __restrict__ Vt)
{
    __shared__ __half ts[64 * 72];
    const int tid = threadIdx.x;
    const int z = blockIdx.y, bB = z >> 3, h = z & 7;
    const int s0 = blockIdx.x * 64;

    #pragma unroll
    for (int j = 0; j < 8; j++) {
        int lin = tid + j * 256;
        int s = lin >> 5, du = lin & 31;
        *(uint32_t*)(ts + s * 72 + du * 2) =
            *(const uint32_t*)(Vh + (size_t)(bB * S_ + s0 + s) * HID_ + h * 64 + du * 2);
    }
    __syncthreads();
    #pragma unroll
    for (int j = 0; j < 8; j++) {
        int lin = tid + j * 256;
        int d = lin >> 5, su = lin & 31;
        __half2 o = __halves2half2(ts[(2 * su) * 72 + d], ts[(2 * su + 1) * 72 + d]);
        *(__half2*)(Vt + ((size_t)z * 64 + d) * S_ + s0 + su * 2) = o;
    }
}

// ---------------------------------------------------------------------------
// attn_A: scores+exp -> rowsum + PV (register P), pm bit-pack (h==0),
// rowinv + X outputs. No attn write.
// ---------------------------------------------------------------------------
#define SMB_Q    0u
#define SMB_K(s) (9216u + (s) * 18432u)
#define SMB_V(s) (64512u + (s) * 17408u)
#define SMB_RS   116736u
#define ATTN_SMEM (117008 + 16)

__global__ void __launch_bounds__(512, 1)
attn_A(const __half* __restrict__ Qh, const __half* __restrict__ Kh,
       const __half* __restrict__ Vtg, const int* __restrict__ mask,
       uint32_t* __restrict__ pm, float* __restrict__ rowinv,
       float* __restrict__ Xo)
{
    extern __shared__ char smg[];
    const uint32_t sb = sptr(smg);

    const int tid = threadIdx.x, lane = tid & 31, w = tid >> 5;
    const int g = lane >> 2, tg = lane & 3;
    const int wm = w & 3, wn = w >> 2;
    const int z = blockIdx.y, strip = blockIdx.x;
    const int bB = z >> 3, h = z & 7;
    const int s0 = strip * 64;
    const bool packM = (h == 0);

    float* rows = (float*)(smg + SMB_RS);
    if (tid < 64) rows[tid] = 0.f;

    const __half* Qsrc = Qh + (size_t)(bB * S_ + s0) * HID_ + h * 64;
    const __half* Ksrc = Kh + (size_t)(bB * S_) * HID_ + h * 64;
    const __half* Vsrc = Vtg + (size_t)z * 64 * S_;

    auto loadKV = [&](int chunk, int st) {
        const int kb = chunk * 128;
        #pragma unroll
        for (int j = 0; j < 2; j++) {
            int idx = tid + j * 512;
            int r = idx >> 3, c16 = idx & 7;
            cp16(sb + SMB_K(st) + (uint32_t)r * 144u + (uint32_t)c16 * 16u,
                 Ksrc + (size_t)(kb + r) * HID_ + c16 * 8);
        }
        #pragma unroll
        for (int j = 0; j < 2; j++) {
            int idx = tid + j * 512;
            int d = idx >> 4, c16 = idx & 15;
            cp16(sb + SMB_V(st) + (uint32_t)d * 272u + (uint32_t)c16 * 16u,
                 Vsrc + (size_t)d * S_ + kb + c16 * 8);
        }
        asm volatile("cp.async.commit_group;");
    };

    {
        int r = tid >> 3, c16 = tid & 7;
        cp16(sb + SMB_Q + (uint32_t)r * 144u + (uint32_t)c16 * 16u,
             Qsrc + (size_t)r * HID_ + c16 * 8);
    }
    loadKV(0, 0);
    loadKV(1, 1);
    asm volatile("cp.async.wait_group 1;");
    __syncthreads();

    const __half* Qs = (const __half*)(smg + SMB_Q);
    unsigned qa[4][4];
    #pragma unroll
    for (int ks = 0; ks < 4; ks++) {
        const __half* qr0 = Qs + (wm * 16 + g) * 72 + ks * 16 + 2 * tg;
        const __half* qr1 = qr0 + 8 * 72;
        qa[ks][0] = *(const uint32_t*)qr0;
        qa[ks][1] = *(const uint32_t*)qr1;
        qa[ks][2] = *(const uint32_t*)(qr0 + 8);
        qa[ks][3] = *(const uint32_t*)(qr1 + 8);
    }

    float pvacc[8][4] = {};
    float rsA = 0.f, rsB = 0.f;

    const int rA = bB * S_ + s0 + wm * 16 + g;

    for (int it = 0; it < 16; it++) {
        const int kb = it * 128;
        const int st = it % 3;

        int2 mA[4], mB[4];
        #pragma unroll
        for (int nt = 0; nt < 4; nt++) {
            int cg = kb + wn * 32 + nt * 8 + 2 * tg;
            mA[nt] = __ldg((const int2*)(mask + (size_t)rA * S_ + cg));
            mB[nt] = __ldg((const int2*)(mask + (size_t)(rA + 8) * S_ + cg));
        }

        if (it > 0) {
            if (it < 15) asm volatile("cp.async.wait_group 1;");
            else         asm volatile("cp.async.wait_group 0;");
            __syncthreads();
        }
        if (it + 2 < 16) loadKV(it + 2, (it + 2) % 3);

        // pm pack (h==0 only): quad-OR into canonical pm[row][kgroup]
        if (packM) {
            uint32_t va = 0, vb = 0;
            #pragma unroll
            for (int nt = 0; nt < 4; nt++) {
                int sh = nt * 8 + 2 * tg;
                va |= ((mA[nt].x != 0) ? 1u : 0u) << sh;
                va |= ((mA[nt].y != 0) ? 1u : 0u) << (sh + 1);
                vb |= ((mB[nt].x != 0) ? 1u : 0u) << sh;
                vb |= ((mB[nt].y != 0) ? 1u : 0u) << (sh + 1);
            }
            va |= __shfl_xor_sync(0xffffffffu, va, 1);
            va |= __shfl_xor_sync(0xffffffffu, va, 2);
            vb |= __shfl_xor_sync(0xffffffffu, vb, 1);
            vb |= __shfl_xor_sync(0xffffffffu, vb, 2);
            if (tg == 0) {
                pm[(uint32_t)rA * 64u + it * 4 + wn] = va;
                pm[(uint32_t)(rA + 8) * 64u + it * 4 + wn] = vb;
            }
        }

        const __half* Ks = (const __half*)(smg + SMB_K(st));
        const __half* Vs = (const __half*)(smg + SMB_V(st));

        float c[4][4] = {};
        #pragma unroll
        for (int ks = 0; ks < 4; ks++) {
            #pragma unroll
            for (int nt = 0; nt < 4; nt++) {
                const __half* kp = Ks + (wn * 32 + nt * 8 + g) * 72 + ks * 16 + 2 * tg;
                unsigned b[2];
                b[0] = *(const uint32_t*)kp;
                b[1] = *(const uint32_t*)(kp + 8);
                mmah(c[nt], qa[ks], b);
            }
        }

        float p[4][4];
        #pragma unroll
        for (int nt = 0; nt < 4; nt++) {
            p[nt][0] = (mA[nt].x != 0) ? __expf(c[nt][0]) : 0.f;
            p[nt][1] = (mA[nt].y != 0) ? __expf(c[nt][1]) : 0.f;
            p[nt][2] = (mB[nt].x != 0) ? __expf(c[nt][2]) : 0.f;
            p[nt][3] = (mB[nt].y != 0) ? __expf(c[nt][3]) : 0.f;
            rsA += p[nt][0] + p[nt][1];
            rsB += p[nt][2] + p[nt][3];
        }

        unsigned pa[2][4];
        #pragma unroll
        for (int k2 = 0; k2 < 2; k2++) {
            __half2 h0 = __floats2half2_rn(p[2 * k2][0], p[2 * k2][1]);
            __half2 h1 = __floats2half2_rn(p[2 * k2][2], p[2 * k2][3]);
            __half2 h2 = __floats2half2_rn(p[2 * k2 + 1][0], p[2 * k2 + 1][1]);
            __half2 h3 = __floats2half2_rn(p[2 * k2 + 1][2], p[2 * k2 + 1][3]);
            pa[k2][0] = *(unsigned*)&h0;
            pa[k2][1] = *(unsigned*)&h1;
            pa[k2][2] = *(unsigned*)&h2;
            pa[k2][3] = *(unsigned*)&h3;
        }

        #pragma unroll
        for (int nt2 = 0; nt2 < 8; nt2++) {
            #pragma unroll
            for (int k2 = 0; k2 < 2; k2++) {
                const __half* vp = Vs + (nt2 * 8 + g) * 136 + wn * 32 + k2 * 16 + 2 * tg;
                unsigned b[2];
                b[0] = *(const uint32_t*)vp;
                b[1] = *(const uint32_t*)(vp + 8);
                mmah(pvacc[nt2], pa[k2], b);
            }
        }
    }

    rsA += __shfl_xor_sync(0xffffffffu, rsA, 1);
    rsA += __shfl_xor_sync(0xffffffffu, rsA, 2);
    rsB += __shfl_xor_sync(0xffffffffu, rsB, 1);
    rsB += __shfl_xor_sync(0xffffffffu, rsB, 2);
    if (tg == 0) {
        atomicAdd(&rows[wm * 16 + g    ], rsA);
        atomicAdd(&rows[wm * 16 + g + 8], rsB);
    }
    __syncthreads();

    if (tid < 64) {
        float inv = 1.0f / rows[tid];
        rows[tid] = inv;
        rowinv[(size_t)z * S_ + s0 + tid] = inv;
    }

    // PV cross-warp reduction: 4 disjoint areas, no atomics
    const uint32_t scrOff[4] = { SMB_V(0), SMB_V(1), SMB_V(2), SMB_K(2) };
    {
        float* sw = (float*)(smg + scrOff[wn]);
        #pragma unroll
        for (int nt2 = 0; nt2 < 8; nt2++) {
            int col = nt2 * 8 + 2 * tg;
            *(float2*)&sw[(wm * 16 + g    ) * 64 + col] =
                make_float2(pvacc[nt2][0], pvacc[nt2][1]);
            *(float2*)&sw[(wm * 16 + g + 8) * 64 + col] =
                make_float2(pvacc[nt2][2], pvacc[nt2][3]);
        }
    }
    __syncthreads();

    {
        int r = tid >> 3, cg = (tid & 7) * 8;
        float4 s0v = make_float4(0, 0, 0, 0), s1v = make_float4(0, 0, 0, 0);
        #pragma unroll
        for (int ww = 0; ww < 4; ww++) {
            const float* sw = (const float*)(smg + scrOff[ww]);
            float4 u0 = *(const float4*)&sw[r * 64 + cg];
            float4 u1 = *(const float4*)&sw[r * 64 + cg + 4];
            s0v.x += u0.x; s0v.y += u0.y; s0v.z += u0.z; s0v.w += u0.w;
            s1v.x += u1.x; s1v.y += u1.y; s1v.z += u1.z; s1v.w += u1.w;
        }
        float inv = rows[r];
        s0v.x *= inv; s0v.y *= inv; s0v.z *= inv; s0v.w *= inv;
        s1v.x *= inv; s1v.y *= inv; s1v.z *= inv; s1v.w *= inv;
        float* xp = Xo + (size_t)(bB * S_ + s0 + r) * HID_ + h * 64 + cg;
        *(float4*)xp = s0v;
        *(float4*)(xp + 4) = s1v;
    }
}

// ---------------------------------------------------------------------------
// attn_B: recompute scores, apply packed mask + inv rowsum, write attn.
// 256 thr (8 warps: wm in {0,1} rows, wn in {0..3} col-slices), 32-row q-tile,
// 3-stage K ring, high occupancy.
// ---------------------------------------------------------------------------
#define BB_Q    0u
#define BB_K(s) (4608u + (s) * 18432u)
#define ATTNB_SMEM (4608 + 3 * 18432 + 16)

__global__ void __launch_bounds__(256)
attn_B(const __half* __restrict__ Qh, const __half* __restrict__ Kh,
       const uint32_t* __restrict__ pm, const float* __restrict__ rowinv,
       float* __restrict__ attn)
{
    extern __shared__ char smg[];
    const uint32_t sb = sptr(smg);

    const int tid = threadIdx.x, lane = tid & 31, w = tid >> 5;
    const int g = lane >> 2, tg = lane & 3;
    const int wm = w & 1, wn = w >> 1;
    const int z = blockIdx.y, strip = blockIdx.x;
    const int bB = z >> 3, h = z & 7;
    const int s0 = strip * 32;

    const __half* Qsrc = Qh + (size_t)(bB * S_ + s0) * HID_ + h * 64;
    const __half* Ksrc = Kh + (size_t)(bB * S_) * HID_ + h * 64;

    auto loadK = [&](int chunk, int st) {
        const int kb = chunk * 128;
        #pragma unroll
        for (int j = 0; j < 4; j++) {
            int idx = tid + j * 256;
            int r = idx >> 3, c16 = idx & 7;
            cp16(sb + BB_K(st) + (uint32_t)r * 144u + (uint32_t)c16 * 16u,
                 Ksrc + (size_t)(kb + r) * HID_ + c16 * 8);
        }
        asm volatile("cp.async.commit_group;");
    };

    // prologue: Q (32 rows) in group 0 with K chunk 0; K chunk 1 in group 1
    {
        int r = tid >> 3, c16 = tid & 7;
        cp16(sb + BB_Q + (uint32_t)r * 144u + (uint32_t)c16 * 16u,
             Qsrc + (size_t)r * HID_ + c16 * 8);
    }
    loadK(0, 0);
    loadK(1, 1);
    asm volatile("cp.async.wait_group 1;");
    __syncthreads();

    const __half* Qs = (const __half*)(smg + BB_Q);
    unsigned qa[4][4];
    #pragma unroll
    for (int ks = 0; ks < 4; ks++) {
        const __half* qr0 = Qs + (wm * 16 + g) * 72 + ks * 16 + 2 * tg;
        const __half* qr1 = qr0 + 8 * 72;
        qa[ks][0] = *(const uint32_t*)qr0;
        qa[ks][1] = *(const uint32_t*)qr1;
        qa[ks][2] = *(const uint32_t*)(qr0 + 8);
        qa[ks][3] = *(const uint32_t*)(qr1 + 8);
    }

    const int rowA = s0 + wm * 16 + g;              // row within sequence
    const float invA = __ldg(rowinv + (size_t)z * S_ + rowA);
    const float invB = __ldg(rowinv + (size_t)z * S_ + rowA + 8);
    const uint32_t pmA = (uint32_t)(bB * S_ + rowA) * 64u;
    const uint32_t pmB = pmA + 8u * 64u;
    const size_t arowA = ((size_t)z * S_ + rowA) * S_;
    const size_t arowB = arowA + 8 * S_;

    for (int it = 0; it < 16; it++) {
        const int kb = it * 128;
        const int st = it % 3;

        const uint32_t wa = __ldg(pm + pmA + it * 4 + wn);
        const uint32_t wb = __ldg(pm + pmB + it * 4 + wn);

        if (it > 0) {
            if (it < 15) asm volatile("cp.async.wait_group 1;");
            else         asm volatile("cp.async.wait_group 0;");
            __syncthreads();
        }
        if (it + 2 < 16) loadK(it + 2, (it + 2) % 3);

        const __half* Ks = (const __half*)(smg + BB_K(st));

        float c[4][4] = {};
        #pragma unroll
        for (int ks = 0; ks < 4; ks++) {
            #pragma unroll
            for (int nt = 0; nt < 4; nt++) {
                const __half* kp = Ks + (wn * 32 + nt * 8 + g) * 72 + ks * 16 + 2 * tg;
                unsigned b[2];
                b[0] = *(const uint32_t*)kp;
                b[1] = *(const uint32_t*)(kp + 8);
                mmah(c[nt], qa[ks], b);
            }
        }

        #pragma unroll
        for (int nt = 0; nt < 4; nt++) {
            int sh = nt * 8 + 2 * tg;
            int cg = kb + wn * 32 + sh;
            float p0 = ((wa >> sh) & 1u)       ? __expf(c[nt][0]) * invA : 0.f;
            float p1 = ((wa >> (sh + 1)) & 1u) ? __expf(c[nt][1]) * invA : 0.f;
            float p2 = ((wb >> sh) & 1u)       ? __expf(c[nt][2]) * invB : 0.f;
            float p3 = ((wb >> (sh + 1)) & 1u) ? __expf(c[nt][3]) * invB : 0.f;
            *(float2*)(attn + arowA + cg) = make_float2(p0, p1);
            *(float2*)(attn + arowB + cg) = make_float2(p2, p3);
        }
    }
}

// ---------------------------------------------------------------------------
// Launch
// ---------------------------------------------------------------------------
extern "C" void kernel_launch(void* const* d_in, const int* in_sizes, int n_in,
                              void* d_out, int out_size)
{
    const float* q    = (const float*)d_in[0];
    const float* k    = (const float*)d_in[1];
    const float* v    = (const float*)d_in[2];
    const int*   mask = (const int*)  d_in[3];
    const float* Wq   = (const float*)d_in[4];
    const float* bq   = (const float*)d_in[5];
    const float* Wk   = (const float*)d_in[6];
    const float* bk   = (const float*)d_in[7];
    const float* Wv   = (const float*)d_in[8];
    const float* bv   = (const float*)d_in[9];
    const float* Wo   = (const float*)d_in[10];
    const float* bo   = (const float*)d_in[11];

    float* out = (float*)d_out;

    __half *Qhp, *Khp, *Vhp, *Vtp;
    float *Xf, *rinv, *scr;
    uint32_t* pmp;
    cudaGetSymbolAddress((void**)&Qhp, g_Qh);
    cudaGetSymbolAddress((void**)&Khp, g_Kh);
    cudaGetSymbolAddress((void**)&Vhp, g_Vh);
    cudaGetSymbolAddress((void**)&Vtp, g_Vt);
    cudaGetSymbolAddress((void**)&Xf,  g_X);
    cudaGetSymbolAddress((void**)&rinv, g_rowinv);
    cudaGetSymbolAddress((void**)&pmp, g_pm);
    cudaGetSymbolAddress((void**)&scr, g_attn_scratch);

    const size_t out_elems  = (size_t)M_ * HID_;
    const size_t attn_elems = (size_t)BH_ * S_ * S_;
    float* attn = ((size_t)out_size >= out_elems + attn_elems) ? out + out_elems : scr;

    cudaFuncSetAttribute(attn_A, cudaFuncAttributeMaxDynamicSharedMemorySize, ATTN_SMEM);
    cudaFuncSetAttribute(attn_B, cudaFuncAttributeMaxDynamicSharedMemorySize, ATTNB_SMEM);
    cudaFuncSetAttribute(proj_tf32, cudaFuncAttributeMaxDynamicSharedMemorySize, PJ_SMEM);

    ProjArgs pq{q, Wq, bq, nullptr, Qhp, 0.125f};
    ProjArgs pk{k, Wk, bk, nullptr, Khp, 1.0f};
    ProjArgs pv{v, Wv, bv, nullptr, Vhp, 1.0f};
    proj_tf32<<<dim3(8, 32, 3), 256, PJ_SMEM>>>(pq, pk, pv);

    vtrans<<<dim3(32, 16), 256>>>(Vhp, Vtp);

    attn_A<<<dim3(32, 16), 512, ATTN_SMEM>>>(Qhp, Khp, Vtp, mask, pmp, rinv, Xf);

    attn_B<<<dim3(64, 16), 256, ATTNB_SMEM>>>(Qhp, Khp, pmp, rinv, attn);

    ProjArgs po{Xf, Wo, bo, out, nullptr, 1.0f};
    proj_tf32<<<dim3(8, 32, 1), 256, PJ_SMEM>>>(po, po, po);
}